// round 4
// baseline (speedup 1.0000x reference)
#include <cuda_runtime.h>
#include <math.h>

// Problem constants (fixed per reference)
#define DN     128      // feature dim
#define HN     256      // hidden dim
#define NNODE  40000
#define NEDGE  640000
#define TM     64       // row tile
#define A2S    260      // A2 smem row stride (floats)
#define YSS    132      // Ys smem row stride (floats)
#define KC     32       // k-chunk (weight staging depth)
#define NT     512      // threads per CTA

typedef unsigned long long u64;

// Scratch (device globals: no allocation allowed)
__device__ float g_agg[NNODE * DN];
__device__ float g_cnt[NNODE];
__device__ int   g_is64;   // 1 if edge_index delivered as raw int64, 0 if int32

__device__ __forceinline__ float silu_f(float x) {
    return x * (1.0f / (1.0f + __expf(-x)));
}

__device__ __forceinline__ float warp_reduce_add(float v) {
#pragma unroll
    for (int o = 16; o > 0; o >>= 1) v += __shfl_xor_sync(0xffffffffu, v, o);
    return v;
}

__device__ __forceinline__ int load_idx(const int* __restrict__ ei, int pos, int is64) {
    return is64 ? ei[2 * pos] : ei[pos];
}

// ---- packed fp32x2 helpers (sm_103a FFMA2 path) ----
__device__ __forceinline__ void ffma2(u64& d, u64 a, u64 b) {
    asm("fma.rn.f32x2 %0, %1, %2, %0;" : "+l"(d) : "l"(a), "l"(b));
}
__device__ __forceinline__ u64 pack_dup(float a) {
    u64 r; asm("mov.b64 %0, {%1, %1};" : "=l"(r) : "f"(a)); return r;
}
__device__ __forceinline__ float2 unpack2(u64 v) {
    float2 r; asm("mov.b64 {%0, %1}, %2;" : "=f"(r.x), "=f"(r.y) : "l"(v)); return r;
}

// Fused 2-layer MLP core on a 64-row tile. 512 threads.
// tx = tid&15 (4 output cols each), ty = tid>>4 in 0..31 (2 rows each).
template <int KIN>
__device__ __forceinline__ void mlp_core(
    float* __restrict__ As, float* __restrict__ A2, float* __restrict__ Bs,
    float* __restrict__ Ys,
    const float* __restrict__ w1, const float* __restrict__ b1,
    const float* __restrict__ w2, const float* __restrict__ b2)
{
    const int tid = threadIdx.x;
    const int tx = tid & 15;
    const int ty = tid >> 4;

    float4* Bs4 = (float4*)Bs;
    const ulonglong2* Bsp = (const ulonglong2*)Bs;

    // ---------------- GEMM1: [TM,KIN] @ [KIN,256] ----------------
    u64 acc[2][8];   // 2 rows x 16 cols (8 packed pairs)
#pragma unroll
    for (int i = 0; i < 2; i++)
#pragma unroll
        for (int j = 0; j < 8; j++) acc[i][j] = 0ull;

    for (int kk = 0; kk < KIN; kk += KC) {
        // stage KC x 256 weight chunk (8192 floats = 2048 float4)
        const float4* wg = (const float4*)(w1 + kk * HN);
#pragma unroll
        for (int t = 0; t < 4; t++) Bs4[tid + t * NT] = wg[tid + t * NT];
        __syncthreads();

#pragma unroll 8
        for (int k = 0; k < KC; k++) {
            u64 a0 = pack_dup(As[(ty * 2 + 0) * KIN + kk + k]);
            u64 a1 = pack_dup(As[(ty * 2 + 1) * KIN + kk + k]);
#pragma unroll
            for (int g = 0; g < 4; g++) {
                ulonglong2 b = Bsp[k * 64 + g * 16 + tx];   // 16B conflict-free
                ffma2(acc[0][g * 2 + 0], a0, b.x);
                ffma2(acc[0][g * 2 + 1], a0, b.y);
                ffma2(acc[1][g * 2 + 0], a1, b.x);
                ffma2(acc[1][g * 2 + 1], a1, b.y);
            }
        }
        __syncthreads();
    }

    // bias + SiLU -> A2 (hidden tile)
#pragma unroll
    for (int i = 0; i < 2; i++) {
        int r = ty * 2 + i;
#pragma unroll
        for (int g = 0; g < 4; g++) {
            float4 bv = ((const float4*)b1)[g * 16 + tx];
            float2 p0 = unpack2(acc[i][g * 2 + 0]);
            float2 p1 = unpack2(acc[i][g * 2 + 1]);
            float4 h;
            h.x = silu_f(p0.x + bv.x);
            h.y = silu_f(p0.y + bv.y);
            h.z = silu_f(p1.x + bv.z);
            h.w = silu_f(p1.y + bv.w);
            ((float4*)(A2 + r * A2S))[g * 16 + tx] = h;
        }
    }
    __syncthreads();

    // ---------------- GEMM2: [TM,256] @ [256,128] ----------------
    u64 acc2[2][4];  // 2 rows x 8 cols (4 packed pairs)
#pragma unroll
    for (int i = 0; i < 2; i++)
#pragma unroll
        for (int j = 0; j < 4; j++) acc2[i][j] = 0ull;

    for (int kk = 0; kk < HN; kk += KC) {
        const float4* wg = (const float4*)(w2 + kk * DN);   // 4096 floats = 1024 float4
#pragma unroll
        for (int t = 0; t < 2; t++) Bs4[tid + t * NT] = wg[tid + t * NT];
        __syncthreads();

#pragma unroll 8
        for (int k = 0; k < KC; k++) {
            u64 a0 = pack_dup(A2[(ty * 2 + 0) * A2S + kk + k]);
            u64 a1 = pack_dup(A2[(ty * 2 + 1) * A2S + kk + k]);
#pragma unroll
            for (int g = 0; g < 2; g++) {
                ulonglong2 b = Bsp[k * 32 + g * 16 + tx];
                ffma2(acc2[0][g * 2 + 0], a0, b.x);
                ffma2(acc2[0][g * 2 + 1], a0, b.y);
                ffma2(acc2[1][g * 2 + 0], a1, b.x);
                ffma2(acc2[1][g * 2 + 1], a1, b.y);
            }
        }
        __syncthreads();
    }

    // bias -> Ys (pre-LN)
#pragma unroll
    for (int i = 0; i < 2; i++) {
        int r = ty * 2 + i;
#pragma unroll
        for (int g = 0; g < 2; g++) {
            float4 bv = ((const float4*)b2)[g * 16 + tx];
            float2 p0 = unpack2(acc2[i][g * 2 + 0]);
            float2 p1 = unpack2(acc2[i][g * 2 + 1]);
            float4 y;
            y.x = p0.x + bv.x;
            y.y = p0.y + bv.y;
            y.z = p1.x + bv.z;
            y.w = p1.y + bv.w;
            ((float4*)(Ys + r * YSS))[g * 16 + tx] = y;
        }
    }
    __syncthreads();
}

// LayerNorm on one row; lane holds cols lane*4..lane*4+3.
__device__ __forceinline__ float4 ln_row(const float* Ys, int rr, int lane,
                                         float4 gm, float4 bt)
{
    float4 v = ((const float4*)(Ys + rr * YSS))[lane];
    float s1 = v.x + v.y + v.z + v.w;
    float s2 = v.x * v.x + v.y * v.y + v.z * v.z + v.w * v.w;
    s1 = warp_reduce_add(s1);
    s2 = warp_reduce_add(s2);
    float mean = s1 * (1.0f / 128.0f);
    float var  = s2 * (1.0f / 128.0f) - mean * mean;
    float rstd = rsqrtf(var + 1e-5f);
    float4 p;
    p.x = (v.x - mean) * rstd * gm.x + bt.x;
    p.y = (v.y - mean) * rstd * gm.y + bt.y;
    p.z = (v.z - mean) * rstd * gm.z + bt.z;
    p.w = (v.w - mean) * rstd * gm.w + bt.w;
    return p;
}

// ------------------------- kernels -------------------------

__global__ void detect_idx_kernel(const int* __restrict__ ei)
{
    __shared__ int any;
    if (threadIdx.x == 0) any = 0;
    __syncthreads();
    for (int i = threadIdx.x; i < 2048; i += blockDim.x)
        if (ei[2 * i + 1] != 0) any = 1;
    __syncthreads();
    if (threadIdx.x == 0) g_is64 = (any == 0) ? 1 : 0;
}

__global__ void zero_scratch_kernel()
{
    int i = blockIdx.x * blockDim.x + threadIdx.x;
    int stride = gridDim.x * blockDim.x;
    for (int j = i; j < NNODE * DN; j += stride) g_agg[j] = 0.0f;
    for (int j = i; j < NNODE; j += stride) g_cnt[j] = 0.0f;
}

__global__ void __launch_bounds__(NT, 1)
edge_kernel(const float* __restrict__ sx, const float* __restrict__ rx,
            const float* __restrict__ ea, const int* __restrict__ ei,
            const float* __restrict__ w1, const float* __restrict__ b1,
            const float* __restrict__ w2, const float* __restrict__ b2,
            const float* __restrict__ gam, const float* __restrict__ bet,
            float* __restrict__ edge_out)
{
    extern __shared__ float smem[];
    float* As = smem;                    // TM * 384
    float* A2 = As + TM * 384;           // TM * A2S
    float* Bs = A2 + TM * A2S;           // KC * 256
    float* Ys = As;                      // alias (As dead before Ys written)

    const int tid = threadIdx.x, lane = tid & 31, warp = tid >> 5;
    const int base = blockIdx.x * TM;
    const int is64 = g_is64;

    // gather: edge_in = [sender_x[src] | receiver_x[dst] | edge_attr]
#pragma unroll
    for (int it = 0; it < 4; it++) {
        int el = warp * 4 + it;
        int e = base + el;
        int s = load_idx(ei, e, is64);
        int d = load_idx(ei, NEDGE + e, is64);
        ((float4*)(As + el * 384))[lane]       = ((const float4*)(sx + (size_t)s * DN))[lane];
        ((float4*)(As + el * 384 + 128))[lane] = ((const float4*)(rx + (size_t)d * DN))[lane];
        ((float4*)(As + el * 384 + 256))[lane] = ((const float4*)(ea + (size_t)e * DN))[lane];
    }
    __syncthreads();

    mlp_core<384>(As, A2, Bs, Ys, w1, b1, w2, b2);

    float4 gm = ((const float4*)gam)[lane];
    float4 bt = ((const float4*)bet)[lane];
#pragma unroll 1
    for (int it = 0; it < 4; it++) {
        int rr = warp * 4 + it;
        int e = base + rr;
        float4 p = ln_row(Ys, rr, lane, gm, bt);
        int d = load_idx(ei, NEDGE + e, is64);
        float4 ev = ((const float4*)(ea + (size_t)e * DN))[lane];
        float4 o;
        o.x = ev.x + p.x; o.y = ev.y + p.y; o.z = ev.z + p.z; o.w = ev.w + p.w;
        ((float4*)(edge_out + (size_t)e * DN))[lane] = o;
        float* ag = g_agg + (size_t)d * DN + lane * 4;
        atomicAdd(ag + 0, p.x);
        atomicAdd(ag + 1, p.y);
        atomicAdd(ag + 2, p.z);
        atomicAdd(ag + 3, p.w);
        if (lane == 0) atomicAdd(&g_cnt[d], 1.0f);
    }
}

__global__ void __launch_bounds__(NT, 1)
node_kernel(const float* __restrict__ rx,
            const float* __restrict__ w1, const float* __restrict__ b1,
            const float* __restrict__ w2, const float* __restrict__ b2,
            const float* __restrict__ gam, const float* __restrict__ bet,
            float* __restrict__ recv_out)
{
    extern __shared__ float smem[];
    float* As = smem;                    // TM * 256
    float* A2 = As + TM * 256;
    float* Bs = A2 + TM * A2S;
    float* Ys = As;

    const int tid = threadIdx.x, lane = tid & 31, warp = tid >> 5;
    const int base = blockIdx.x * TM;

#pragma unroll
    for (int it = 0; it < 4; it++) {
        int nl = warp * 4 + it;
        int n = base + nl;
        ((float4*)(As + nl * 256))[lane] = ((const float4*)(rx + (size_t)n * DN))[lane];
        float c = g_cnt[n];
        float inv = 1.0f / fmaxf(c, 1.0f);
        float4 a = ((const float4*)(g_agg + (size_t)n * DN))[lane];
        a.x *= inv; a.y *= inv; a.z *= inv; a.w *= inv;
        ((float4*)(As + nl * 256 + 128))[lane] = a;
    }
    __syncthreads();

    mlp_core<256>(As, A2, Bs, Ys, w1, b1, w2, b2);

    float4 gm = ((const float4*)gam)[lane];
    float4 bt = ((const float4*)bet)[lane];
#pragma unroll 1
    for (int it = 0; it < 4; it++) {
        int rr = warp * 4 + it;
        int n = base + rr;
        float4 p = ln_row(Ys, rr, lane, gm, bt);
        float4 xv = ((const float4*)(rx + (size_t)n * DN))[lane];
        float4 o;
        o.x = xv.x + p.x; o.y = xv.y + p.y; o.z = xv.z + p.z; o.w = xv.w + p.w;
        ((float4*)(recv_out + (size_t)n * DN))[lane] = o;
    }
}

__global__ void __launch_bounds__(NT, 1)
sender_kernel(const float* __restrict__ sx,
              const float* __restrict__ w1, const float* __restrict__ b1,
              const float* __restrict__ w2, const float* __restrict__ b2,
              const float* __restrict__ gam, const float* __restrict__ bet,
              float* __restrict__ send_out)
{
    extern __shared__ float smem[];
    float* As = smem;                    // TM*128 input; Ys alias needs TM*YSS
    float* A2 = smem + TM * YSS;
    float* Bs = A2 + TM * A2S;
    float* Ys = As;

    const int tid = threadIdx.x, lane = tid & 31, warp = tid >> 5;
    const int base = blockIdx.x * TM;

#pragma unroll
    for (int it = 0; it < 4; it++) {
        int nl = warp * 4 + it;
        int n = base + nl;
        ((float4*)(As + nl * 128))[lane] = ((const float4*)(sx + (size_t)n * DN))[lane];
    }
    __syncthreads();

    mlp_core<128>(As, A2, Bs, Ys, w1, b1, w2, b2);

    float4 gm = ((const float4*)gam)[lane];
    float4 bt = ((const float4*)bet)[lane];
#pragma unroll 1
    for (int it = 0; it < 4; it++) {
        int rr = warp * 4 + it;
        int n = base + rr;
        float4 p = ln_row(Ys, rr, lane, gm, bt);
        float4 xv = ((const float4*)(sx + (size_t)n * DN))[lane];
        float4 o;
        o.x = xv.x + p.x; o.y = xv.y + p.y; o.z = xv.z + p.z; o.w = xv.w + p.w;
        ((float4*)(send_out + (size_t)n * DN))[lane] = o;
    }
}

// ------------------------- launch -------------------------

extern "C" void kernel_launch(void* const* d_in, const int* in_sizes, int n_in,
                              void* d_out, int out_size)
{
    const float* sx    = (const float*)d_in[0];
    const float* rx    = (const float*)d_in[1];
    const float* ea    = (const float*)d_in[2];
    const int*   ei    = (const int*)d_in[3];
    const float* ew1   = (const float*)d_in[4];
    const float* eb1   = (const float*)d_in[5];
    const float* ew2   = (const float*)d_in[6];
    const float* eb2   = (const float*)d_in[7];
    const float* eg    = (const float*)d_in[8];
    const float* ebeta = (const float*)d_in[9];
    const float* nw1   = (const float*)d_in[10];
    const float* nb1   = (const float*)d_in[11];
    const float* nw2   = (const float*)d_in[12];
    const float* nb2   = (const float*)d_in[13];
    const float* ng    = (const float*)d_in[14];
    const float* nbeta = (const float*)d_in[15];
    const float* sw1   = (const float*)d_in[16];
    const float* sb1   = (const float*)d_in[17];
    const float* sw2   = (const float*)d_in[18];
    const float* sb2   = (const float*)d_in[19];
    const float* sg    = (const float*)d_in[20];
    const float* sbeta = (const float*)d_in[21];

    float* out = (float*)d_out;
    float* send_out = out;                                  // [N, D]
    float* recv_out = out + (size_t)NNODE * DN;             // [N, D]
    float* edge_out = out + (size_t)2 * NNODE * DN;         // [E, D]

    const int smemE = (TM * 384 + TM * A2S + KC * HN) * (int)sizeof(float);
    const int smemN = (TM * 256 + TM * A2S + KC * HN) * (int)sizeof(float);
    const int smemS = (TM * YSS + TM * A2S + KC * HN) * (int)sizeof(float);
    cudaFuncSetAttribute(edge_kernel,   cudaFuncAttributeMaxDynamicSharedMemorySize, smemE);
    cudaFuncSetAttribute(node_kernel,   cudaFuncAttributeMaxDynamicSharedMemorySize, smemN);
    cudaFuncSetAttribute(sender_kernel, cudaFuncAttributeMaxDynamicSharedMemorySize, smemS);

    detect_idx_kernel<<<1, 256>>>(ei);
    zero_scratch_kernel<<<296, 256>>>();

    edge_kernel<<<NEDGE / TM, NT, smemE>>>(
        sx, rx, ea, ei, ew1, eb1, ew2, eb2, eg, ebeta, edge_out);

    sender_kernel<<<NNODE / TM, NT, smemS>>>(
        sx, sw1, sb1, sw2, sb2, sg, sbeta, send_out);

    node_kernel<<<NNODE / TM, NT, smemN>>>(
        rx, nw1, nb1, nw2, nb2, ng, nbeta, recv_out);
}

// round 7
// speedup vs baseline: 2.0168x; 2.0168x over previous
#include <cuda_runtime.h>
#include <cuda_bf16.h>
#include <math.h>

// Problem constants
#define DN     128
#define HN     256
#define NNODE  40000
#define NEDGE  640000
#define TM     64       // row tile for fp32 node/sender kernels
#define A2S    260
#define YSS    132
#define KC     32
#define EB     128      // edge rows per CTA (mma kernel)

typedef unsigned long long u64;
typedef unsigned int u32;

// ------------------------- device globals (no allocation allowed) -------------------------
__device__ float g_agg[NNODE * DN];
__device__ float g_cnt[NNODE];
__device__ int   g_is64;

// Pre-transposed + bf16-split edge weights (written by prep kernel each launch)
// W1T: [256 n][384 k] bf16, k-major.  u32 index = n*192 + k/2
__device__ u32 g_w1t_hi[256 * 192];
__device__ u32 g_w1t_lo[256 * 192];
// W2T: [128 n][256 k] bf16, k-major.  u32 index = n*128 + k/2
__device__ u32 g_w2t_hi[128 * 128];
__device__ u32 g_w2t_lo[128 * 128];

// ------------------------- helpers -------------------------
__device__ __forceinline__ float silu_f(float x) {
    return x * (1.0f / (1.0f + __expf(-x)));
}
__device__ __forceinline__ float warp_reduce_add(float v) {
#pragma unroll
    for (int o = 16; o > 0; o >>= 1) v += __shfl_xor_sync(0xffffffffu, v, o);
    return v;
}
__device__ __forceinline__ int load_idx(const int* __restrict__ ei, int pos, int is64) {
    return is64 ? ei[2 * pos] : ei[pos];
}
__device__ __forceinline__ void ffma2(u64& d, u64 a, u64 b) {
    asm("fma.rn.f32x2 %0, %1, %2, %0;" : "+l"(d) : "l"(a), "l"(b));
}
__device__ __forceinline__ u64 pack_dup(float a) {
    u64 r; asm("mov.b64 %0, {%1, %1};" : "=l"(r) : "f"(a)); return r;
}
__device__ __forceinline__ float2 unpack2(u64 v) {
    float2 r; asm("mov.b64 {%0, %1}, %2;" : "=f"(r.x), "=f"(r.y) : "l"(v)); return r;
}
// word = [bf16(v1) << 16 | bf16(v0)]
__device__ __forceinline__ u32 pack_bf16(float v0, float v1) {
    u32 r; asm("cvt.rn.bf16x2.f32 %0, %1, %2;" : "=r"(r) : "f"(v1), "f"(v0)); return r;
}
__device__ __forceinline__ u32 smem_u32(const void* p) {
    u32 a; asm("{ .reg .u64 t; cvta.to.shared.u64 t, %1; cvt.u32.u64 %0, t; }" : "=r"(a) : "l"(p));
    return a;
}
__device__ __forceinline__ void ldsm4(u32 a, u32& r0, u32& r1, u32& r2, u32& r3) {
    asm volatile("ldmatrix.sync.aligned.m8n8.x4.shared.b16 {%0,%1,%2,%3}, [%4];"
                 : "=r"(r0), "=r"(r1), "=r"(r2), "=r"(r3) : "r"(a));
}
__device__ __forceinline__ void mma_bf16(float* c, const u32* a, u32 b0, u32 b1) {
    asm volatile(
        "mma.sync.aligned.m16n8k16.row.col.f32.bf16.bf16.f32 "
        "{%0,%1,%2,%3}, {%4,%5,%6,%7}, {%8,%9}, {%0,%1,%2,%3};"
        : "+f"(c[0]), "+f"(c[1]), "+f"(c[2]), "+f"(c[3])
        : "r"(a[0]), "r"(a[1]), "r"(a[2]), "r"(a[3]), "r"(b0), "r"(b1));
}

// ==================== fp32 FFMA2 MLP core (node/sender, 256 threads, proven R3) ====================
template <int KIN>
__device__ __forceinline__ void mlp_core(
    float* __restrict__ As, float* __restrict__ A2, float* __restrict__ Bs,
    float* __restrict__ Ys,
    const float* __restrict__ w1, const float* __restrict__ b1,
    const float* __restrict__ w2, const float* __restrict__ b2)
{
    const int tid = threadIdx.x;
    const int tx = tid & 15;
    const int ty = tid >> 4;

    float4* Bs4 = (float4*)Bs;
    const ulonglong2* Bsp = (const ulonglong2*)Bs;

    u64 acc[4][8];
#pragma unroll
    for (int i = 0; i < 4; i++)
#pragma unroll
        for (int j = 0; j < 8; j++) acc[i][j] = 0ull;

    for (int kk = 0; kk < KIN; kk += KC) {
        const float4* wg = (const float4*)(w1 + kk * HN);
#pragma unroll
        for (int t = 0; t < 8; t++) Bs4[tid + t * 256] = wg[tid + t * 256];
        __syncthreads();
#pragma unroll 8
        for (int k = 0; k < KC; k++) {
            u64 a2v[4];
#pragma unroll
            for (int i = 0; i < 4; i++)
                a2v[i] = pack_dup(As[(ty * 4 + i) * KIN + kk + k]);
#pragma unroll
            for (int g = 0; g < 4; g++) {
                ulonglong2 b = Bsp[k * 64 + g * 16 + tx];
#pragma unroll
                for (int i = 0; i < 4; i++) {
                    ffma2(acc[i][g * 2 + 0], a2v[i], b.x);
                    ffma2(acc[i][g * 2 + 1], a2v[i], b.y);
                }
            }
        }
        __syncthreads();
    }

#pragma unroll
    for (int i = 0; i < 4; i++) {
        int r = ty * 4 + i;
#pragma unroll
        for (int g = 0; g < 4; g++) {
            float4 bv = ((const float4*)b1)[g * 16 + tx];
            float2 p0 = unpack2(acc[i][g * 2 + 0]);
            float2 p1 = unpack2(acc[i][g * 2 + 1]);
            float4 h;
            h.x = silu_f(p0.x + bv.x);
            h.y = silu_f(p0.y + bv.y);
            h.z = silu_f(p1.x + bv.z);
            h.w = silu_f(p1.y + bv.w);
            ((float4*)(A2 + r * A2S))[g * 16 + tx] = h;
        }
    }
    __syncthreads();

    u64 acc2[4][4];
#pragma unroll
    for (int i = 0; i < 4; i++)
#pragma unroll
        for (int j = 0; j < 4; j++) acc2[i][j] = 0ull;

    for (int kk = 0; kk < HN; kk += KC) {
        const float4* wg = (const float4*)(w2 + kk * DN);
#pragma unroll
        for (int t = 0; t < 4; t++) Bs4[tid + t * 256] = wg[tid + t * 256];
        __syncthreads();
#pragma unroll 8
        for (int k = 0; k < KC; k++) {
            u64 a2v[4];
#pragma unroll
            for (int i = 0; i < 4; i++)
                a2v[i] = pack_dup(A2[(ty * 4 + i) * A2S + kk + k]);
#pragma unroll
            for (int g = 0; g < 2; g++) {
                ulonglong2 b = Bsp[k * 32 + g * 16 + tx];
#pragma unroll
                for (int i = 0; i < 4; i++) {
                    ffma2(acc2[i][g * 2 + 0], a2v[i], b.x);
                    ffma2(acc2[i][g * 2 + 1], a2v[i], b.y);
                }
            }
        }
        __syncthreads();
    }

#pragma unroll
    for (int i = 0; i < 4; i++) {
        int r = ty * 4 + i;
#pragma unroll
        for (int g = 0; g < 2; g++) {
            float4 bv = ((const float4*)b2)[g * 16 + tx];
            float2 p0 = unpack2(acc2[i][g * 2 + 0]);
            float2 p1 = unpack2(acc2[i][g * 2 + 1]);
            float4 y;
            y.x = p0.x + bv.x;
            y.y = p0.y + bv.y;
            y.z = p1.x + bv.z;
            y.w = p1.y + bv.w;
            ((float4*)(Ys + r * YSS))[g * 16 + tx] = y;
        }
    }
    __syncthreads();
}

__device__ __forceinline__ float4 ln_row(const float* Ys, int rr, int lane,
                                         float4 gm, float4 bt)
{
    float4 v = ((const float4*)(Ys + rr * YSS))[lane];
    float s1 = v.x + v.y + v.z + v.w;
    float s2 = v.x * v.x + v.y * v.y + v.z * v.z + v.w * v.w;
    s1 = warp_reduce_add(s1);
    s2 = warp_reduce_add(s2);
    float mean = s1 * (1.0f / 128.0f);
    float var  = s2 * (1.0f / 128.0f) - mean * mean;
    float rstd = rsqrtf(var + 1e-5f);
    float4 p;
    p.x = (v.x - mean) * rstd * gm.x + bt.x;
    p.y = (v.y - mean) * rstd * gm.y + bt.y;
    p.z = (v.z - mean) * rstd * gm.z + bt.z;
    p.w = (v.w - mean) * rstd * gm.w + bt.w;
    return p;
}

// ------------------------- utility kernels -------------------------
__global__ void detect_idx_kernel(const int* __restrict__ ei)
{
    __shared__ int any;
    if (threadIdx.x == 0) any = 0;
    __syncthreads();
    for (int i = threadIdx.x; i < 2048; i += blockDim.x)
        if (ei[2 * i + 1] != 0) any = 1;
    __syncthreads();
    if (threadIdx.x == 0) g_is64 = (any == 0) ? 1 : 0;
}

__global__ void zero_scratch_kernel()
{
    int i = blockIdx.x * blockDim.x + threadIdx.x;
    int stride = gridDim.x * blockDim.x;
    for (int j = i; j < NNODE * DN; j += stride) g_agg[j] = 0.0f;
    for (int j = i; j < NNODE; j += stride) g_cnt[j] = 0.0f;
}

// Transpose + bf16-split the edge weights into k-major globals.
__global__ void prep_weights_kernel(const float* __restrict__ ew1,
                                    const float* __restrict__ ew2)
{
    int i = blockIdx.x * blockDim.x + threadIdx.x;
    const int T1 = 256 * 192;
    if (i < T1) {
        int n = i / 192, kp = i % 192;
        float v0 = ew1[(size_t)(2 * kp) * HN + n];
        float v1 = ew1[(size_t)(2 * kp + 1) * HN + n];
        float h0 = __bfloat162float(__float2bfloat16_rn(v0));
        float h1 = __bfloat162float(__float2bfloat16_rn(v1));
        g_w1t_hi[i] = pack_bf16(v0, v1);
        g_w1t_lo[i] = pack_bf16(v0 - h0, v1 - h1);
    } else {
        int i2 = i - T1;
        if (i2 < 128 * 128) {
            int n = i2 / 128, kp = i2 % 128;
            float v0 = ew2[(size_t)(2 * kp) * DN + n];
            float v1 = ew2[(size_t)(2 * kp + 1) * DN + n];
            float h0 = __bfloat162float(__float2bfloat16_rn(v0));
            float h1 = __bfloat162float(__float2bfloat16_rn(v1));
            g_w2t_hi[i2] = pack_bf16(v0, v1);
            g_w2t_lo[i2] = pack_bf16(v0 - h0, v1 - h1);
        }
    }
}

// ==================== mma.sync edge kernel ====================
// smem (bytes from base):
//  phase1: A1hi [128][136h] @0 (34816)  A1lo @34816  B1 [256][136h] @69632 (69632) end 139264
//  phase2: A2hi [128][264h] @0 (67584)  A2lo @67584  B2 [128][264h] @135168 (67584) end 202752
//  Ys     [128][132 f32] @0 (67584)
#define SA1H 0
#define SA1L 34816
#define SB1  69632
#define SA2H 0
#define SA2L 67584
#define SB2  135168
#define ESMEM 202752
#define ST1  272    // byte stride, GEMM1 tiles (136 halves)
#define ST2  528    // byte stride, GEMM2 tiles (264 halves)

// one (A,B) sweep of GEMM1: warp tile m32 x n64, K=128 (8 ksteps)
__device__ __forceinline__ void sweep1(u32 aBase, u32 bBase, float (&acc)[2][8][4])
{
#pragma unroll
    for (int ks = 0; ks < 8; ks++) {
        u32 A0[4], A1[4];
        ldsm4(aBase + ks * 32, A0[0], A0[1], A0[2], A0[3]);
        ldsm4(aBase + 16 * ST1 + ks * 32, A1[0], A1[1], A1[2], A1[3]);
#pragma unroll
        for (int p = 0; p < 4; p++) {
            u32 b0, b1, b2, b3;
            ldsm4(bBase + p * 16 * ST1 + ks * 32, b0, b1, b2, b3);
            mma_bf16(acc[0][2 * p + 0], A0, b0, b1);
            mma_bf16(acc[0][2 * p + 1], A0, b2, b3);
            mma_bf16(acc[1][2 * p + 0], A1, b0, b1);
            mma_bf16(acc[1][2 * p + 1], A1, b2, b3);
        }
    }
}

// one (A,B) sweep of GEMM2: warp tile m32 x n32, K=256 (16 ksteps)
__device__ __forceinline__ void sweep2(u32 aBase, u32 bBase, float (&acc)[2][4][4])
{
#pragma unroll
    for (int ks = 0; ks < 16; ks++) {
        u32 A0[4], A1[4];
        ldsm4(aBase + ks * 32, A0[0], A0[1], A0[2], A0[3]);
        ldsm4(aBase + 16 * ST2 + ks * 32, A1[0], A1[1], A1[2], A1[3]);
#pragma unroll
        for (int p = 0; p < 2; p++) {
            u32 b0, b1, b2, b3;
            ldsm4(bBase + p * 16 * ST2 + ks * 32, b0, b1, b2, b3);
            mma_bf16(acc[0][2 * p + 0], A0, b0, b1);
            mma_bf16(acc[0][2 * p + 1], A0, b2, b3);
            mma_bf16(acc[1][2 * p + 0], A1, b0, b1);
            mma_bf16(acc[1][2 * p + 1], A1, b2, b3);
        }
    }
}

__global__ void __launch_bounds__(512, 1)
edge_kernel_mma(const float* __restrict__ sx, const float* __restrict__ rx,
                const float* __restrict__ ea, const int* __restrict__ ei,
                const float* __restrict__ b1, const float* __restrict__ b2,
                const float* __restrict__ gam, const float* __restrict__ bet,
                float* __restrict__ edge_out)
{
    extern __shared__ char smc[];
    const u32 S = smem_u32(smc);

    const int tid = threadIdx.x, lane = tid & 31, warp = tid >> 5;
    const int base = blockIdx.x * EB;
    const int is64 = g_is64;

    const int r8 = lane & 7, q8 = lane >> 3;
    const int g = lane >> 2, tg = lane & 3;

    // ---------------- GEMM1 ----------------
    const int wm = (warp >> 2) * 32;     // 0,32,64,96
    const int wn = (warp & 3) * 64;      // 0,64,128,192

    // ldmatrix lane addresses (fixed across chunks)
    const u32 a1hiA = S + SA1H + (u32)(wm + r8 + (q8 & 1) * 8) * ST1 + (u32)((q8 >> 1) * 8) * 2;
    const u32 a1loA = S + SA1L + (u32)(wm + r8 + (q8 & 1) * 8) * ST1 + (u32)((q8 >> 1) * 8) * 2;
    const u32 b1A   = S + SB1  + (u32)(wn + r8 + (q8 >> 1) * 8) * ST1 + (u32)((q8 & 1) * 8) * 2;

    float acc[2][8][4];
#pragma unroll
    for (int i = 0; i < 2; i++)
#pragma unroll
        for (int j = 0; j < 8; j++)
#pragma unroll
            for (int t = 0; t < 4; t++) acc[i][j][t] = 0.0f;

    // gather source pointers
    const int grow = tid >> 2, gq = tid & 3;
    const int e0 = base + grow;
    const int si = load_idx(ei, e0, is64);
    const int di = load_idx(ei, NEDGE + e0, is64);

    for (int c = 0; c < 3; c++) {
        __syncthreads();   // previous chunk fully consumed

        // gather + split A chunk: 4 threads per row, 32 cols each
        {
            const float* src = (c == 0) ? (sx + (size_t)si * DN)
                             : (c == 1) ? (rx + (size_t)di * DN)
                                        : (ea + (size_t)e0 * DN);
#pragma unroll
            for (int it = 0; it < 4; it++) {
                int k0 = gq * 32 + it * 8;
                float4 f0 = ((const float4*)(src + k0))[0];
                float4 f1 = ((const float4*)(src + k0))[1];
                float v[8] = { f0.x, f0.y, f0.z, f0.w, f1.x, f1.y, f1.z, f1.w };
                u32 hw[4], lw[4];
#pragma unroll
                for (int j = 0; j < 4; j++) {
                    float a0 = v[2 * j], a1 = v[2 * j + 1];
                    float h0 = __bfloat162float(__float2bfloat16_rn(a0));
                    float h1 = __bfloat162float(__float2bfloat16_rn(a1));
                    hw[j] = pack_bf16(a0, a1);
                    lw[j] = pack_bf16(a0 - h0, a1 - h1);
                }
                u32 off = (u32)grow * ST1 + (u32)k0 * 2;
                *(uint4*)(smc + SA1H + off) = make_uint4(hw[0], hw[1], hw[2], hw[3]);
                *(uint4*)(smc + SA1L + off) = make_uint4(lw[0], lw[1], lw[2], lw[3]);
            }
        }
        // stage B1 hi chunk: 256 rows x 16 uint4
        {
            const uint4* gsrc = (const uint4*)g_w1t_hi;
#pragma unroll
            for (int t = 0; t < 8; t++) {
                int idx = tid + t * 512;
                int n = idx >> 4, s = idx & 15;
                uint4 v = gsrc[n * 48 + c * 16 + s];
                *(uint4*)(smc + SB1 + (u32)n * ST1 + (u32)s * 16) = v;
            }
        }
        __syncthreads();

        sweep1(a1hiA, b1A, acc);      // Ahi x Bhi
        sweep1(a1loA, b1A, acc);      // Alo x Bhi
        __syncthreads();

        // stage B1 lo chunk
        {
            const uint4* gsrc = (const uint4*)g_w1t_lo;
#pragma unroll
            for (int t = 0; t < 8; t++) {
                int idx = tid + t * 512;
                int n = idx >> 4, s = idx & 15;
                uint4 v = gsrc[n * 48 + c * 16 + s];
                *(uint4*)(smc + SB1 + (u32)n * ST1 + (u32)s * 16) = v;
            }
        }
        __syncthreads();

        sweep1(a1hiA, b1A, acc);      // Ahi x Blo
    }
    __syncthreads();   // all GEMM1 reads done; A2/B2 regions may be written

    // ---------------- epilogue1: bias + SiLU + split -> A2 ----------------
#pragma unroll
    for (int i = 0; i < 2; i++) {
        int row0 = wm + i * 16 + g;
#pragma unroll
        for (int j = 0; j < 8; j++) {
            int n0 = wn + j * 8 + tg * 2;
            float bv0 = b1[n0], bv1 = b1[n0 + 1];
            float h0 = silu_f(acc[i][j][0] + bv0);
            float h1 = silu_f(acc[i][j][1] + bv1);
            float h2 = silu_f(acc[i][j][2] + bv0);
            float h3 = silu_f(acc[i][j][3] + bv1);
            float t0 = __bfloat162float(__float2bfloat16_rn(h0));
            float t1 = __bfloat162float(__float2bfloat16_rn(h1));
            float t2 = __bfloat162float(__float2bfloat16_rn(h2));
            float t3 = __bfloat162float(__float2bfloat16_rn(h3));
            u32 off0 = (u32)row0 * ST2 + (u32)n0 * 2;
            u32 off1 = (u32)(row0 + 8) * ST2 + (u32)n0 * 2;
            *(u32*)(smc + SA2H + off0) = pack_bf16(h0, h1);
            *(u32*)(smc + SA2L + off0) = pack_bf16(h0 - t0, h1 - t1);
            *(u32*)(smc + SA2H + off1) = pack_bf16(h2, h3);
            *(u32*)(smc + SA2L + off1) = pack_bf16(h2 - t2, h3 - t3);
        }
    }
    // stage B2 hi: 128 rows x 32 uint4
    {
        const uint4* gsrc = (const uint4*)g_w2t_hi;
#pragma unroll
        for (int t = 0; t < 8; t++) {
            int idx = tid + t * 512;
            int n = idx >> 5, s = idx & 31;
            uint4 v = gsrc[n * 32 + s];
            *(uint4*)(smc + SB2 + (u32)n * ST2 + (u32)s * 16) = v;
        }
    }
    __syncthreads();

    // ---------------- GEMM2 ----------------
    const int wm2 = (warp >> 2) * 32;
    const int wn2 = (warp & 3) * 32;
    const u32 a2hiA = S + SA2H + (u32)(wm2 + r8 + (q8 & 1) * 8) * ST2 + (u32)((q8 >> 1) * 8) * 2;
    const u32 a2loA = S + SA2L + (u32)(wm2 + r8 + (q8 & 1) * 8) * ST2 + (u32)((q8 >> 1) * 8) * 2;
    const u32 b2A   = S + SB2  + (u32)(wn2 + r8 + (q8 >> 1) * 8) * ST2 + (u32)((q8 & 1) * 8) * 2;

    float acc2[2][4][4];
#pragma unroll
    for (int i = 0; i < 2; i++)
#pragma unroll
        for (int j = 0; j < 4; j++)
#pragma unroll
            for (int t = 0; t < 4; t++) acc2[i][j][t] = 0.0f;

    sweep2(a2hiA, b2A, acc2);
    sweep2(a2loA, b2A, acc2);
    __syncthreads();
    {
        const uint4* gsrc = (const uint4*)g_w2t_lo;
#pragma unroll
        for (int t = 0; t < 8; t++) {
            int idx = tid + t * 512;
            int n = idx >> 5, s = idx & 31;
            uint4 v = gsrc[n * 32 + s];
            *(uint4*)(smc + SB2 + (u32)n * ST2 + (u32)s * 16) = v;
        }
    }
    __syncthreads();
    sweep2(a2hiA, b2A, acc2);
    __syncthreads();   // all GEMM2 reads done; Ys region may be written

    // ---------------- epilogue2a: bias -> Ys fp32 ----------------
#pragma unroll
    for (int i = 0; i < 2; i++) {
        int row0 = wm2 + i * 16 + g;
#pragma unroll
        for (int j = 0; j < 4; j++) {
            int n0 = wn2 + j * 8 + tg * 2;
            float bv0 = b2[n0], bv1 = b2[n0 + 1];
            float2 y0 = make_float2(acc2[i][j][0] + bv0, acc2[i][j][1] + bv1);
            float2 y1 = make_float2(acc2[i][j][2] + bv0, acc2[i][j][3] + bv1);
            *(float2*)(smc + (u32)row0 * ST2 + (u32)n0 * 4)       = y0;
            *(float2*)(smc + (u32)(row0 + 8) * ST2 + (u32)n0 * 4) = y1;
        }
    }
    __syncthreads();

    // ---------------- epilogue2b: LN + residual + atomic scatter ----------------
    {
        const float* Ys = (const float*)smc;
        float4 gm = ((const float4*)gam)[lane];
        float4 bt = ((const float4*)bet)[lane];
#pragma unroll 1
        for (int it = 0; it < 8; it++) {
            int rr = warp * 8 + it;
            int e = base + rr;
            float4 p = ln_row(Ys, rr, lane, gm, bt);
            int d = load_idx(ei, NEDGE + e, is64);
            float4 ev = ((const float4*)(ea + (size_t)e * DN))[lane];
            float4 o;
            o.x = ev.x + p.x; o.y = ev.y + p.y; o.z = ev.z + p.z; o.w = ev.w + p.w;
            ((float4*)(edge_out + (size_t)e * DN))[lane] = o;
            float* ag = g_agg + (size_t)d * DN + lane * 4;
            atomicAdd(ag + 0, p.x);
            atomicAdd(ag + 1, p.y);
            atomicAdd(ag + 2, p.z);
            atomicAdd(ag + 3, p.w);
            if (lane == 0) atomicAdd(&g_cnt[d], 1.0f);
        }
    }
}

// ==================== node / sender (proven R3) ====================
__global__ void __launch_bounds__(256, 1)
node_kernel(const float* __restrict__ rx,
            const float* __restrict__ w1, const float* __restrict__ b1,
            const float* __restrict__ w2, const float* __restrict__ b2,
            const float* __restrict__ gam, const float* __restrict__ bet,
            float* __restrict__ recv_out)
{
    extern __shared__ float smem[];
    float* As = smem;
    float* A2 = As + TM * 256;
    float* Bs = A2 + TM * A2S;
    float* Ys = As;

    const int tid = threadIdx.x, lane = tid & 31, warp = tid >> 5;
    const int base = blockIdx.x * TM;

#pragma unroll
    for (int it = 0; it < 8; it++) {
        int nl = warp * 8 + it;
        int n = base + nl;
        ((float4*)(As + nl * 256))[lane] = ((const float4*)(rx + (size_t)n * DN))[lane];
        float c = g_cnt[n];
        float inv = 1.0f / fmaxf(c, 1.0f);
        float4 a = ((const float4*)(g_agg + (size_t)n * DN))[lane];
        a.x *= inv; a.y *= inv; a.z *= inv; a.w *= inv;
        ((float4*)(As + nl * 256 + 128))[lane] = a;
    }
    __syncthreads();

    mlp_core<256>(As, A2, Bs, Ys, w1, b1, w2, b2);

    float4 gm = ((const float4*)gam)[lane];
    float4 bt = ((const float4*)bet)[lane];
#pragma unroll 1
    for (int it = 0; it < 8; it++) {
        int rr = warp * 8 + it;
        int n = base + rr;
        float4 p = ln_row(Ys, rr, lane, gm, bt);
        float4 xv = ((const float4*)(rx + (size_t)n * DN))[lane];
        float4 o;
        o.x = xv.x + p.x; o.y = xv.y + p.y; o.z = xv.z + p.z; o.w = xv.w + p.w;
        ((float4*)(recv_out + (size_t)n * DN))[lane] = o;
    }
}

__global__ void __launch_bounds__(256, 1)
sender_kernel(const float* __restrict__ sx,
              const float* __restrict__ w1, const float* __restrict__ b1,
              const float* __restrict__ w2, const float* __restrict__ b2,
              const float* __restrict__ gam, const float* __restrict__ bet,
              float* __restrict__ send_out)
{
    extern __shared__ float smem[];
    float* As = smem;
    float* A2 = smem + TM * YSS;
    float* Bs = A2 + TM * A2S;
    float* Ys = As;

    const int tid = threadIdx.x, lane = tid & 31, warp = tid >> 5;
    const int base = blockIdx.x * TM;

#pragma unroll
    for (int it = 0; it < 8; it++) {
        int nl = warp * 8 + it;
        int n = base + nl;
        ((float4*)(As + nl * 128))[lane] = ((const float4*)(sx + (size_t)n * DN))[lane];
    }
    __syncthreads();

    mlp_core<128>(As, A2, Bs, Ys, w1, b1, w2, b2);

    float4 gm = ((const float4*)gam)[lane];
    float4 bt = ((const float4*)bet)[lane];
#pragma unroll 1
    for (int it = 0; it < 8; it++) {
        int rr = warp * 8 + it;
        int n = base + rr;
        float4 p = ln_row(Ys, rr, lane, gm, bt);
        float4 xv = ((const float4*)(sx + (size_t)n * DN))[lane];
        float4 o;
        o.x = xv.x + p.x; o.y = xv.y + p.y; o.z = xv.z + p.z; o.w = xv.w + p.w;
        ((float4*)(send_out + (size_t)n * DN))[lane] = o;
    }
}

// ------------------------- launch -------------------------
extern "C" void kernel_launch(void* const* d_in, const int* in_sizes, int n_in,
                              void* d_out, int out_size)
{
    const float* sx    = (const float*)d_in[0];
    const float* rx    = (const float*)d_in[1];
    const float* ea    = (const float*)d_in[2];
    const int*   ei    = (const int*)d_in[3];
    const float* ew1   = (const float*)d_in[4];
    const float* eb1   = (const float*)d_in[5];
    const float* ew2   = (const float*)d_in[6];
    const float* eb2   = (const float*)d_in[7];
    const float* eg    = (const float*)d_in[8];
    const float* ebeta = (const float*)d_in[9];
    const float* nw1   = (const float*)d_in[10];
    const float* nb1   = (const float*)d_in[11];
    const float* nw2   = (const float*)d_in[12];
    const float* nb2   = (const float*)d_in[13];
    const float* ng    = (const float*)d_in[14];
    const float* nbeta = (const float*)d_in[15];
    const float* sw1   = (const float*)d_in[16];
    const float* sb1   = (const float*)d_in[17];
    const float* sw2   = (const float*)d_in[18];
    const float* sb2   = (const float*)d_in[19];
    const float* sg    = (const float*)d_in[20];
    const float* sbeta = (const float*)d_in[21];

    float* out = (float*)d_out;
    float* send_out = out;
    float* recv_out = out + (size_t)NNODE * DN;
    float* edge_out = out + (size_t)2 * NNODE * DN;

    const int smemN = (TM * 256 + TM * A2S + KC * HN) * (int)sizeof(float);
    const int smemS = (TM * YSS + TM * A2S + KC * HN) * (int)sizeof(float);
    cudaFuncSetAttribute(edge_kernel_mma, cudaFuncAttributeMaxDynamicSharedMemorySize, ESMEM);
    cudaFuncSetAttribute(node_kernel,     cudaFuncAttributeMaxDynamicSharedMemorySize, smemN);
    cudaFuncSetAttribute(sender_kernel,   cudaFuncAttributeMaxDynamicSharedMemorySize, smemS);

    detect_idx_kernel<<<1, 256>>>(ei);
    prep_weights_kernel<<<256, 256>>>(ew1, ew2);
    zero_scratch_kernel<<<296, 256>>>();

    edge_kernel_mma<<<NEDGE / EB, 512, ESMEM>>>(
        sx, rx, ea, ei, eb1, eb2, eg, ebeta, edge_out);

    sender_kernel<<<NNODE / TM, 256, smemS>>>(
        sx, sw1, sb1, sw2, sb2, sg, sbeta, send_out);

    node_kernel<<<NNODE / TM, 256, smemN>>>(
        rx, nw1, nb1, nw2, nb2, ng, nbeta, recv_out);
}

// round 8
// speedup vs baseline: 2.1295x; 1.0559x over previous
#include <cuda_runtime.h>
#include <cuda_bf16.h>
#include <math.h>

// Problem constants
#define DN     128
#define HN     256
#define NNODE  40000
#define NEDGE  640000
#define TM     64       // row tile for fp32 node/sender kernels
#define A2S    260
#define YSS    132
#define KC     32
#define EB     64       // edge rows per CTA (mma kernel)

typedef unsigned long long u64;
typedef unsigned int u32;

// ------------------------- device globals (no allocation allowed) -------------------------
__device__ float g_agg[NNODE * DN];
__device__ float g_cnt[NNODE];
__device__ int   g_is64;

// Pre-transposed + bf16-split edge weights (written by prep kernel each launch)
// W1T: [256 n][384 k] bf16, k-major.  u32 index = n*192 + k/2
__device__ u32 g_w1t_hi[256 * 192];
__device__ u32 g_w1t_lo[256 * 192];
// W2T: [128 n][256 k] bf16, k-major.  u32 index = n*128 + k/2
__device__ u32 g_w2t_hi[128 * 128];
__device__ u32 g_w2t_lo[128 * 128];

// ------------------------- helpers -------------------------
__device__ __forceinline__ float silu_f(float x) {
    return x * (1.0f / (1.0f + __expf(-x)));
}
__device__ __forceinline__ float warp_reduce_add(float v) {
#pragma unroll
    for (int o = 16; o > 0; o >>= 1) v += __shfl_xor_sync(0xffffffffu, v, o);
    return v;
}
__device__ __forceinline__ int load_idx(const int* __restrict__ ei, int pos, int is64) {
    return is64 ? ei[2 * pos] : ei[pos];
}
__device__ __forceinline__ void ffma2(u64& d, u64 a, u64 b) {
    asm("fma.rn.f32x2 %0, %1, %2, %0;" : "+l"(d) : "l"(a), "l"(b));
}
__device__ __forceinline__ u64 pack_dup(float a) {
    u64 r; asm("mov.b64 %0, {%1, %1};" : "=l"(r) : "f"(a)); return r;
}
__device__ __forceinline__ float2 unpack2(u64 v) {
    float2 r; asm("mov.b64 {%0, %1}, %2;" : "=f"(r.x), "=f"(r.y) : "l"(v)); return r;
}
// word = [bf16(v1) << 16 | bf16(v0)]
__device__ __forceinline__ u32 pack_bf16(float v0, float v1) {
    u32 r; asm("cvt.rn.bf16x2.f32 %0, %1, %2;" : "=r"(r) : "f"(v1), "f"(v0)); return r;
}
__device__ __forceinline__ u32 smem_u32(const void* p) {
    u32 a; asm("{ .reg .u64 t; cvta.to.shared.u64 t, %1; cvt.u32.u64 %0, t; }" : "=r"(a) : "l"(p));
    return a;
}
__device__ __forceinline__ void ldsm4(u32 a, u32& r0, u32& r1, u32& r2, u32& r3) {
    asm volatile("ldmatrix.sync.aligned.m8n8.x4.shared.b16 {%0,%1,%2,%3}, [%4];"
                 : "=r"(r0), "=r"(r1), "=r"(r2), "=r"(r3) : "r"(a));
}
__device__ __forceinline__ void mma_bf16(float* c, const u32* a, u32 b0, u32 b1) {
    asm volatile(
        "mma.sync.aligned.m16n8k16.row.col.f32.bf16.bf16.f32 "
        "{%0,%1,%2,%3}, {%4,%5,%6,%7}, {%8,%9}, {%0,%1,%2,%3};"
        : "+f"(c[0]), "+f"(c[1]), "+f"(c[2]), "+f"(c[3])
        : "r"(a[0]), "r"(a[1]), "r"(a[2]), "r"(a[3]), "r"(b0), "r"(b1));
}
__device__ __forceinline__ void cpasync16(u32 dst, const void* src) {
    asm volatile("cp.async.cg.shared.global [%0], [%1], 16;" :: "r"(dst), "l"(src));
}
__device__ __forceinline__ void cp_wait_all() {
    asm volatile("cp.async.commit_group;");
    asm volatile("cp.async.wait_group 0;" ::: "memory");
}

// ==================== fp32 FFMA2 MLP core (node/sender, 256 threads, proven R3) ====================
template <int KIN>
__device__ __forceinline__ void mlp_core(
    float* __restrict__ As, float* __restrict__ A2, float* __restrict__ Bs,
    float* __restrict__ Ys,
    const float* __restrict__ w1, const float* __restrict__ b1,
    const float* __restrict__ w2, const float* __restrict__ b2)
{
    const int tid = threadIdx.x;
    const int tx = tid & 15;
    const int ty = tid >> 4;

    float4* Bs4 = (float4*)Bs;
    const ulonglong2* Bsp = (const ulonglong2*)Bs;

    u64 acc[4][8];
#pragma unroll
    for (int i = 0; i < 4; i++)
#pragma unroll
        for (int j = 0; j < 8; j++) acc[i][j] = 0ull;

    for (int kk = 0; kk < KIN; kk += KC) {
        const float4* wg = (const float4*)(w1 + kk * HN);
#pragma unroll
        for (int t = 0; t < 8; t++) Bs4[tid + t * 256] = wg[tid + t * 256];
        __syncthreads();
#pragma unroll 8
        for (int k = 0; k < KC; k++) {
            u64 a2v[4];
#pragma unroll
            for (int i = 0; i < 4; i++)
                a2v[i] = pack_dup(As[(ty * 4 + i) * KIN + kk + k]);
#pragma unroll
            for (int g = 0; g < 4; g++) {
                ulonglong2 b = Bsp[k * 64 + g * 16 + tx];
#pragma unroll
                for (int i = 0; i < 4; i++) {
                    ffma2(acc[i][g * 2 + 0], a2v[i], b.x);
                    ffma2(acc[i][g * 2 + 1], a2v[i], b.y);
                }
            }
        }
        __syncthreads();
    }

#pragma unroll
    for (int i = 0; i < 4; i++) {
        int r = ty * 4 + i;
#pragma unroll
        for (int g = 0; g < 4; g++) {
            float4 bv = ((const float4*)b1)[g * 16 + tx];
            float2 p0 = unpack2(acc[i][g * 2 + 0]);
            float2 p1 = unpack2(acc[i][g * 2 + 1]);
            float4 h;
            h.x = silu_f(p0.x + bv.x);
            h.y = silu_f(p0.y + bv.y);
            h.z = silu_f(p1.x + bv.z);
            h.w = silu_f(p1.y + bv.w);
            ((float4*)(A2 + r * A2S))[g * 16 + tx] = h;
        }
    }
    __syncthreads();

    u64 acc2[4][4];
#pragma unroll
    for (int i = 0; i < 4; i++)
#pragma unroll
        for (int j = 0; j < 4; j++) acc2[i][j] = 0ull;

    for (int kk = 0; kk < HN; kk += KC) {
        const float4* wg = (const float4*)(w2 + kk * DN);
#pragma unroll
        for (int t = 0; t < 4; t++) Bs4[tid + t * 256] = wg[tid + t * 256];
        __syncthreads();
#pragma unroll 8
        for (int k = 0; k < KC; k++) {
            u64 a2v[4];
#pragma unroll
            for (int i = 0; i < 4; i++)
                a2v[i] = pack_dup(A2[(ty * 4 + i) * A2S + kk + k]);
#pragma unroll
            for (int g = 0; g < 2; g++) {
                ulonglong2 b = Bsp[k * 32 + g * 16 + tx];
#pragma unroll
                for (int i = 0; i < 4; i++) {
                    ffma2(acc2[i][g * 2 + 0], a2v[i], b.x);
                    ffma2(acc2[i][g * 2 + 1], a2v[i], b.y);
                }
            }
        }
        __syncthreads();
    }

#pragma unroll
    for (int i = 0; i < 4; i++) {
        int r = ty * 4 + i;
#pragma unroll
        for (int g = 0; g < 2; g++) {
            float4 bv = ((const float4*)b2)[g * 16 + tx];
            float2 p0 = unpack2(acc2[i][g * 2 + 0]);
            float2 p1 = unpack2(acc2[i][g * 2 + 1]);
            float4 y;
            y.x = p0.x + bv.x;
            y.y = p0.y + bv.y;
            y.z = p1.x + bv.z;
            y.w = p1.y + bv.w;
            ((float4*)(Ys + r * YSS))[g * 16 + tx] = y;
        }
    }
    __syncthreads();
}

__device__ __forceinline__ float4 ln_row(const float* Ys, int rr, int lane,
                                         float4 gm, float4 bt)
{
    float4 v = ((const float4*)(Ys + rr * YSS))[lane];
    float s1 = v.x + v.y + v.z + v.w;
    float s2 = v.x * v.x + v.y * v.y + v.z * v.z + v.w * v.w;
    s1 = warp_reduce_add(s1);
    s2 = warp_reduce_add(s2);
    float mean = s1 * (1.0f / 128.0f);
    float var  = s2 * (1.0f / 128.0f) - mean * mean;
    float rstd = rsqrtf(var + 1e-5f);
    float4 p;
    p.x = (v.x - mean) * rstd * gm.x + bt.x;
    p.y = (v.y - mean) * rstd * gm.y + bt.y;
    p.z = (v.z - mean) * rstd * gm.z + bt.z;
    p.w = (v.w - mean) * rstd * gm.w + bt.w;
    return p;
}

// ------------------------- utility kernels -------------------------
__global__ void detect_idx_kernel(const int* __restrict__ ei)
{
    __shared__ int any;
    if (threadIdx.x == 0) any = 0;
    __syncthreads();
    for (int i = threadIdx.x; i < 2048; i += blockDim.x)
        if (ei[2 * i + 1] != 0) any = 1;
    __syncthreads();
    if (threadIdx.x == 0) g_is64 = (any == 0) ? 1 : 0;
}

__global__ void zero_scratch_kernel()
{
    int i = blockIdx.x * blockDim.x + threadIdx.x;
    int stride = gridDim.x * blockDim.x;
    for (int j = i; j < NNODE * DN; j += stride) g_agg[j] = 0.0f;
    for (int j = i; j < NNODE; j += stride) g_cnt[j] = 0.0f;
}

// Transpose + bf16-split the edge weights into k-major globals.
__global__ void prep_weights_kernel(const float* __restrict__ ew1,
                                    const float* __restrict__ ew2)
{
    int i = blockIdx.x * blockDim.x + threadIdx.x;
    const int T1 = 256 * 192;
    if (i < T1) {
        int n = i / 192, kp = i % 192;
        float v0 = ew1[(size_t)(2 * kp) * HN + n];
        float v1 = ew1[(size_t)(2 * kp + 1) * HN + n];
        float h0 = __bfloat162float(__float2bfloat16_rn(v0));
        float h1 = __bfloat162float(__float2bfloat16_rn(v1));
        g_w1t_hi[i] = pack_bf16(v0, v1);
        g_w1t_lo[i] = pack_bf16(v0 - h0, v1 - h1);
    } else {
        int i2 = i - T1;
        if (i2 < 128 * 128) {
            int n = i2 / 128, kp = i2 % 128;
            float v0 = ew2[(size_t)(2 * kp) * DN + n];
            float v1 = ew2[(size_t)(2 * kp + 1) * DN + n];
            float h0 = __bfloat162float(__float2bfloat16_rn(v0));
            float h1 = __bfloat162float(__float2bfloat16_rn(v1));
            g_w2t_hi[i2] = pack_bf16(v0, v1);
            g_w2t_lo[i2] = pack_bf16(v0 - h0, v1 - h1);
        }
    }
}

// ==================== mma.sync edge kernel (256 thr, 64 rows, 2 CTAs/SM) ====================
// smem (bytes):
//  phase1: A1hi [64][136h] @0 (17408)  A1lo @17408  B1 [256][136h] @34816 (69632) end 104448
//  phase2: A2hi [64][264h] @0 (33792)  A2lo @33792  B2half [64][264h] @67584 (33792) end 101376
//  Ys     [64][132 f32] @0 (33792)
#define SA1H 0
#define SA1L 17408
#define SB1  34816
#define SA2H 0
#define SA2L 33792
#define SB2  67584
#define ESMEM 104448
#define ST1  272    // byte stride, GEMM1 tiles (136 halves)
#define ST2  528    // byte stride, GEMM2 tiles (264 halves)

// one (A,B) sweep of GEMM1: warp tile m32 x n64, K=128 (8 ksteps)
__device__ __forceinline__ void sweep1(u32 aBase, u32 bBase, float (&acc)[2][8][4])
{
#pragma unroll
    for (int ks = 0; ks < 8; ks++) {
        u32 A0[4], A1[4];
        ldsm4(aBase + ks * 32, A0[0], A0[1], A0[2], A0[3]);
        ldsm4(aBase + 16 * ST1 + ks * 32, A1[0], A1[1], A1[2], A1[3]);
#pragma unroll
        for (int p = 0; p < 4; p++) {
            u32 b0, b1, b2, b3;
            ldsm4(bBase + p * 16 * ST1 + ks * 32, b0, b1, b2, b3);
            mma_bf16(acc[0][2 * p + 0], A0, b0, b1);
            mma_bf16(acc[0][2 * p + 1], A0, b2, b3);
            mma_bf16(acc[1][2 * p + 0], A1, b0, b1);
            mma_bf16(acc[1][2 * p + 1], A1, b2, b3);
        }
    }
}

// one (A,B) sweep of GEMM2: warp tile m16 x n32, K=256 (16 ksteps)
__device__ __forceinline__ void sweep2(u32 aBase, u32 bBase, float (&acc)[4][4])
{
#pragma unroll
    for (int ks = 0; ks < 16; ks++) {
        u32 A0[4];
        ldsm4(aBase + ks * 32, A0[0], A0[1], A0[2], A0[3]);
#pragma unroll
        for (int p = 0; p < 2; p++) {
            u32 b0, b1, b2, b3;
            ldsm4(bBase + p * 16 * ST2 + ks * 32, b0, b1, b2, b3);
            mma_bf16(acc[2 * p + 0], A0, b0, b1);
            mma_bf16(acc[2 * p + 1], A0, b2, b3);
        }
    }
}

__global__ void __launch_bounds__(256, 2)
edge_kernel_mma(const float* __restrict__ sx, const float* __restrict__ rx,
                const float* __restrict__ ea, const int* __restrict__ ei,
                const float* __restrict__ b1, const float* __restrict__ b2,
                const float* __restrict__ gam, const float* __restrict__ bet,
                float* __restrict__ edge_out)
{
    extern __shared__ char smc[];
    const u32 S = smem_u32(smc);

    const int tid = threadIdx.x, lane = tid & 31, warp = tid >> 5;
    const int base = blockIdx.x * EB;
    const int is64 = g_is64;

    const int r8 = lane & 7, q8 = lane >> 3;
    const int g = lane >> 2, tg = lane & 3;

    // ---------------- GEMM1 ----------------
    const int wm = (warp >> 2) * 32;     // 0,32
    const int wn = (warp & 3) * 64;      // 0,64,128,192

    const u32 a1hiA = S + SA1H + (u32)(wm + r8 + (q8 & 1) * 8) * ST1 + (u32)((q8 >> 1) * 8) * 2;
    const u32 a1loA = S + SA1L + (u32)(wm + r8 + (q8 & 1) * 8) * ST1 + (u32)((q8 >> 1) * 8) * 2;
    const u32 b1A   = S + SB1  + (u32)(wn + r8 + (q8 >> 1) * 8) * ST1 + (u32)((q8 & 1) * 8) * 2;

    float acc[2][8][4];
#pragma unroll
    for (int i = 0; i < 2; i++)
#pragma unroll
        for (int j = 0; j < 8; j++)
#pragma unroll
            for (int t = 0; t < 4; t++) acc[i][j][t] = 0.0f;

    // gather source (4 threads per row, 32 cols each)
    const int grow = tid >> 2, gq = tid & 3;
    const int e0 = base + grow;
    const int si = load_idx(ei, e0, is64);
    const int di = load_idx(ei, NEDGE + e0, is64);

    for (int c = 0; c < 3; c++) {
        __syncthreads();   // previous chunk fully consumed

        // stage B1 hi chunk via cp.async: 256 rows x 16 uint4
        {
            const uint4* gsrc = (const uint4*)g_w1t_hi;
#pragma unroll
            for (int t = 0; t < 16; t++) {
                int idx = tid + t * 256;
                int n = idx >> 4, s = idx & 15;
                cpasync16(S + SB1 + (u32)n * ST1 + (u32)s * 16, gsrc + n * 48 + c * 16 + s);
            }
        }
        // gather + split A chunk
        {
            const float* src = (c == 0) ? (sx + (size_t)si * DN)
                             : (c == 1) ? (rx + (size_t)di * DN)
                                        : (ea + (size_t)e0 * DN);
#pragma unroll
            for (int it = 0; it < 4; it++) {
                int k0 = gq * 32 + it * 8;
                float4 f0 = ((const float4*)(src + k0))[0];
                float4 f1 = ((const float4*)(src + k0))[1];
                float v[8] = { f0.x, f0.y, f0.z, f0.w, f1.x, f1.y, f1.z, f1.w };
                u32 hw[4], lw[4];
#pragma unroll
                for (int j = 0; j < 4; j++) {
                    float a0 = v[2 * j], a1 = v[2 * j + 1];
                    float h0 = __bfloat162float(__float2bfloat16_rn(a0));
                    float h1 = __bfloat162float(__float2bfloat16_rn(a1));
                    hw[j] = pack_bf16(a0, a1);
                    lw[j] = pack_bf16(a0 - h0, a1 - h1);
                }
                u32 off = (u32)grow * ST1 + (u32)k0 * 2;
                *(uint4*)(smc + SA1H + off) = make_uint4(hw[0], hw[1], hw[2], hw[3]);
                *(uint4*)(smc + SA1L + off) = make_uint4(lw[0], lw[1], lw[2], lw[3]);
            }
        }
        cp_wait_all();
        __syncthreads();

        sweep1(a1hiA, b1A, acc);      // Ahi x Bhi
        sweep1(a1loA, b1A, acc);      // Alo x Bhi
        __syncthreads();

        // stage B1 lo chunk
        {
            const uint4* gsrc = (const uint4*)g_w1t_lo;
#pragma unroll
            for (int t = 0; t < 16; t++) {
                int idx = tid + t * 256;
                int n = idx >> 4, s = idx & 15;
                cpasync16(S + SB1 + (u32)n * ST1 + (u32)s * 16, gsrc + n * 48 + c * 16 + s);
            }
        }
        cp_wait_all();
        __syncthreads();

        sweep1(a1hiA, b1A, acc);      // Ahi x Blo
    }
    __syncthreads();   // all GEMM1 reads done; A2/B2 regions may be written

    // ---------------- epilogue1: bias + SiLU + split -> A2 ----------------
#pragma unroll
    for (int i = 0; i < 2; i++) {
        int row0 = wm + i * 16 + g;
#pragma unroll
        for (int j = 0; j < 8; j++) {
            int n0 = wn + j * 8 + tg * 2;
            float bv0 = b1[n0], bv1 = b1[n0 + 1];
            float h0 = silu_f(acc[i][j][0] + bv0);
            float h1 = silu_f(acc[i][j][1] + bv1);
            float h2 = silu_f(acc[i][j][2] + bv0);
            float h3 = silu_f(acc[i][j][3] + bv1);
            float t0 = __bfloat162float(__float2bfloat16_rn(h0));
            float t1 = __bfloat162float(__float2bfloat16_rn(h1));
            float t2 = __bfloat162float(__float2bfloat16_rn(h2));
            float t3 = __bfloat162float(__float2bfloat16_rn(h3));
            u32 off0 = (u32)row0 * ST2 + (u32)n0 * 2;
            u32 off1 = (u32)(row0 + 8) * ST2 + (u32)n0 * 2;
            *(u32*)(smc + SA2H + off0) = pack_bf16(h0, h1);
            *(u32*)(smc + SA2L + off0) = pack_bf16(h0 - t0, h1 - t1);
            *(u32*)(smc + SA2H + off1) = pack_bf16(h2, h3);
            *(u32*)(smc + SA2L + off1) = pack_bf16(h2 - t2, h3 - t3);
        }
    }

    // ---------------- GEMM2: two 64-col n-halves ----------------
    const int wm2 = (warp >> 1) * 16;   // 0,16,32,48
    const int wn2 = (warp & 1) * 32;    // 0,32
    const u32 a2hiA = S + SA2H + (u32)(wm2 + r8 + (q8 & 1) * 8) * ST2 + (u32)((q8 >> 1) * 8) * 2;
    const u32 a2loA = S + SA2L + (u32)(wm2 + r8 + (q8 & 1) * 8) * ST2 + (u32)((q8 >> 1) * 8) * 2;
    const u32 b2A   = S + SB2  + (u32)(wn2 + r8 + (q8 >> 1) * 8) * ST2 + (u32)((q8 & 1) * 8) * 2;

    float acc2[2][4][4];
#pragma unroll
    for (int h = 0; h < 2; h++)
#pragma unroll
        for (int j = 0; j < 4; j++)
#pragma unroll
            for (int t = 0; t < 4; t++) acc2[h][j][t] = 0.0f;

    for (int h = 0; h < 2; h++) {
        // stage B2 hi half: rows h*64..h*64+63, 32 uint4 each
        {
            const uint4* gsrc = (const uint4*)g_w2t_hi;
#pragma unroll
            for (int t = 0; t < 8; t++) {
                int idx = tid + t * 256;
                int n = idx >> 5, s = idx & 31;
                cpasync16(S + SB2 + (u32)n * ST2 + (u32)s * 16, gsrc + (h * 64 + n) * 32 + s);
            }
        }
        cp_wait_all();
        __syncthreads();

        sweep2(a2hiA, b2A, acc2[h]);
        sweep2(a2loA, b2A, acc2[h]);
        __syncthreads();

        {
            const uint4* gsrc = (const uint4*)g_w2t_lo;
#pragma unroll
            for (int t = 0; t < 8; t++) {
                int idx = tid + t * 256;
                int n = idx >> 5, s = idx & 31;
                cpasync16(S + SB2 + (u32)n * ST2 + (u32)s * 16, gsrc + (h * 64 + n) * 32 + s);
            }
        }
        cp_wait_all();
        __syncthreads();

        sweep2(a2hiA, b2A, acc2[h]);
        __syncthreads();
    }

    // ---------------- epilogue2a: bias -> Ys fp32 (aliases A2hi region) ----------------
#pragma unroll
    for (int h = 0; h < 2; h++) {
        int row0 = wm2 + g;
#pragma unroll
        for (int j = 0; j < 4; j++) {
            int n0 = h * 64 + wn2 + j * 8 + tg * 2;
            float bv0 = b2[n0], bv1 = b2[n0 + 1];
            float2 y0 = make_float2(acc2[h][j][0] + bv0, acc2[h][j][1] + bv1);
            float2 y1 = make_float2(acc2[h][j][2] + bv0, acc2[h][j][3] + bv1);
            *(float2*)(smc + (u32)row0 * ST2 + (u32)n0 * 4)       = y0;
            *(float2*)(smc + (u32)(row0 + 8) * ST2 + (u32)n0 * 4) = y1;
        }
    }
    __syncthreads();

    // ---------------- epilogue2b: LN + residual + atomic scatter ----------------
    {
        const float* Ys = (const float*)smc;
        float4 gm = ((const float4*)gam)[lane];
        float4 bt = ((const float4*)bet)[lane];
#pragma unroll 1
        for (int it = 0; it < 8; it++) {
            int rr = warp * 8 + it;
            int e = base + rr;
            float4 p = ln_row(Ys, rr, lane, gm, bt);
            int d = load_idx(ei, NEDGE + e, is64);
            float4 ev = ((const float4*)(ea + (size_t)e * DN))[lane];
            float4 o;
            o.x = ev.x + p.x; o.y = ev.y + p.y; o.z = ev.z + p.z; o.w = ev.w + p.w;
            ((float4*)(edge_out + (size_t)e * DN))[lane] = o;
            float* ag = g_agg + (size_t)d * DN + lane * 4;
            atomicAdd(ag + 0, p.x);
            atomicAdd(ag + 1, p.y);
            atomicAdd(ag + 2, p.z);
            atomicAdd(ag + 3, p.w);
            if (lane == 0) atomicAdd(&g_cnt[d], 1.0f);
        }
    }
}

// ==================== node / sender (proven R3) ====================
__global__ void __launch_bounds__(256, 1)
node_kernel(const float* __restrict__ rx,
            const float* __restrict__ w1, const float* __restrict__ b1,
            const float* __restrict__ w2, const float* __restrict__ b2,
            const float* __restrict__ gam, const float* __restrict__ bet,
            float* __restrict__ recv_out)
{
    extern __shared__ float smem[];
    float* As = smem;
    float* A2 = As + TM * 256;
    float* Bs = A2 + TM * A2S;
    float* Ys = As;

    const int tid = threadIdx.x, lane = tid & 31, warp = tid >> 5;
    const int base = blockIdx.x * TM;

#pragma unroll
    for (int it = 0; it < 8; it++) {
        int nl = warp * 8 + it;
        int n = base + nl;
        ((float4*)(As + nl * 256))[lane] = ((const float4*)(rx + (size_t)n * DN))[lane];
        float c = g_cnt[n];
        float inv = 1.0f / fmaxf(c, 1.0f);
        float4 a = ((const float4*)(g_agg + (size_t)n * DN))[lane];
        a.x *= inv; a.y *= inv; a.z *= inv; a.w *= inv;
        ((float4*)(As + nl * 256 + 128))[lane] = a;
    }
    __syncthreads();

    mlp_core<256>(As, A2, Bs, Ys, w1, b1, w2, b2);

    float4 gm = ((const float4*)gam)[lane];
    float4 bt = ((const float4*)bet)[lane];
#pragma unroll 1
    for (int it = 0; it < 8; it++) {
        int rr = warp * 8 + it;
        int n = base + rr;
        float4 p = ln_row(Ys, rr, lane, gm, bt);
        float4 xv = ((const float4*)(rx + (size_t)n * DN))[lane];
        float4 o;
        o.x = xv.x + p.x; o.y = xv.y + p.y; o.z = xv.z + p.z; o.w = xv.w + p.w;
        ((float4*)(recv_out + (size_t)n * DN))[lane] = o;
    }
}

__global__ void __launch_bounds__(256, 1)
sender_kernel(const float* __restrict__ sx,
              const float* __restrict__ w1, const float* __restrict__ b1,
              const float* __restrict__ w2, const float* __restrict__ b2,
              const float* __restrict__ gam, const float* __restrict__ bet,
              float* __restrict__ send_out)
{
    extern __shared__ float smem[];
    float* As = smem;
    float* A2 = smem + TM * YSS;
    float* Bs = A2 + TM * A2S;
    float* Ys = As;

    const int tid = threadIdx.x, lane = tid & 31, warp = tid >> 5;
    const int base = blockIdx.x * TM;

#pragma unroll
    for (int it = 0; it < 8; it++) {
        int nl = warp * 8 + it;
        int n = base + nl;
        ((float4*)(As + nl * 128))[lane] = ((const float4*)(sx + (size_t)n * DN))[lane];
    }
    __syncthreads();

    mlp_core<128>(As, A2, Bs, Ys, w1, b1, w2, b2);

    float4 gm = ((const float4*)gam)[lane];
    float4 bt = ((const float4*)bet)[lane];
#pragma unroll 1
    for (int it = 0; it < 8; it++) {
        int rr = warp * 8 + it;
        int n = base + rr;
        float4 p = ln_row(Ys, rr, lane, gm, bt);
        float4 xv = ((const float4*)(sx + (size_t)n * DN))[lane];
        float4 o;
        o.x = xv.x + p.x; o.y = xv.y + p.y; o.z = xv.z + p.z; o.w = xv.w + p.w;
        ((float4*)(send_out + (size_t)n * DN))[lane] = o;
    }
}

// ------------------------- launch -------------------------
extern "C" void kernel_launch(void* const* d_in, const int* in_sizes, int n_in,
                              void* d_out, int out_size)
{
    const float* sx    = (const float*)d_in[0];
    const float* rx    = (const float*)d_in[1];
    const float* ea    = (const float*)d_in[2];
    const int*   ei    = (const int*)d_in[3];
    const float* ew1   = (const float*)d_in[4];
    const float* eb1   = (const float*)d_in[5];
    const float* ew2   = (const float*)d_in[6];
    const float* eb2   = (const float*)d_in[7];
    const float* eg    = (const float*)d_in[8];
    const float* ebeta = (const float*)d_in[9];
    const float* nw1   = (const float*)d_in[10];
    const float* nb1   = (const float*)d_in[11];
    const float* nw2   = (const float*)d_in[12];
    const float* nb2   = (const float*)d_in[13];
    const float* ng    = (const float*)d_in[14];
    const float* nbeta = (const float*)d_in[15];
    const float* sw1   = (const float*)d_in[16];
    const float* sb1   = (const float*)d_in[17];
    const float* sw2   = (const float*)d_in[18];
    const float* sb2   = (const float*)d_in[19];
    const float* sg    = (const float*)d_in[20];
    const float* sbeta = (const float*)d_in[21];

    float* out = (float*)d_out;
    float* send_out = out;
    float* recv_out = out + (size_t)NNODE * DN;
    float* edge_out = out + (size_t)2 * NNODE * DN;

    const int smemN = (TM * 256 + TM * A2S + KC * HN) * (int)sizeof(float);
    const int smemS = (TM * YSS + TM * A2S + KC * HN) * (int)sizeof(float);
    cudaFuncSetAttribute(edge_kernel_mma, cudaFuncAttributeMaxDynamicSharedMemorySize, ESMEM);
    cudaFuncSetAttribute(node_kernel,     cudaFuncAttributeMaxDynamicSharedMemorySize, smemN);
    cudaFuncSetAttribute(sender_kernel,   cudaFuncAttributeMaxDynamicSharedMemorySize, smemS);

    detect_idx_kernel<<<1, 256>>>(ei);
    prep_weights_kernel<<<256, 256>>>(ew1, ew2);
    zero_scratch_kernel<<<296, 256>>>();

    edge_kernel_mma<<<NEDGE / EB, 256, ESMEM>>>(
        sx, rx, ea, ei, eb1, eb2, eg, ebeta, edge_out);

    sender_kernel<<<NNODE / TM, 256, smemS>>>(
        sx, sw1, sb1, sw2, sb2, sg, sbeta, send_out);

    node_kernel<<<NNODE / TM, 256, smemN>>>(
        rx, nw1, nb1, nw2, nb2, ng, nbeta, recv_out);
}

// round 12
// speedup vs baseline: 2.3787x; 1.1170x over previous
#include <cuda_runtime.h>
#include <cuda_bf16.h>
#include <cuda_fp16.h>
#include <math.h>

// Problem constants
#define DN     128
#define HN     256
#define NNODE  40000
#define NEDGE  640000
#define TM     64       // row tile for fp32 node/sender kernels
#define A2S    260
#define YSS    132
#define KC     32
#define EB     64       // edge rows per CTA (mma kernel)

typedef unsigned long long u64;
typedef unsigned int u32;

// ------------------------- device globals (no allocation allowed) -------------------------
__device__ float g_agg[NNODE * DN];
__device__ float g_cnt[NNODE];
__device__ int   g_is64;

// Pre-transposed fp16 edge weights (written by prep kernel each launch)
// W1T: [256 n][384 k] fp16, k-major.  u32 index = n*192 + k/2
__device__ u32 g_w1t[256 * 192];
// W2T: [128 n][256 k] fp16, k-major.  u32 index = n*128 + k/2
__device__ u32 g_w2t[128 * 128];

// ------------------------- helpers -------------------------
__device__ __forceinline__ float silu_f(float x) {
    return x * (1.0f / (1.0f + __expf(-x)));
}
__device__ __forceinline__ float warp_reduce_add(float v) {
#pragma unroll
    for (int o = 16; o > 0; o >>= 1) v += __shfl_xor_sync(0xffffffffu, v, o);
    return v;
}
__device__ __forceinline__ int load_idx(const int* __restrict__ ei, int pos, int is64) {
    return is64 ? ei[2 * pos] : ei[pos];
}
__device__ __forceinline__ void ffma2(u64& d, u64 a, u64 b) {
    asm("fma.rn.f32x2 %0, %1, %2, %0;" : "+l"(d) : "l"(a), "l"(b));
}
__device__ __forceinline__ u64 pack_dup(float a) {
    u64 r; asm("mov.b64 %0, {%1, %1};" : "=l"(r) : "f"(a)); return r;
}
__device__ __forceinline__ float2 unpack2(u64 v) {
    float2 r; asm("mov.b64 {%0, %1}, %2;" : "=f"(r.x), "=f"(r.y) : "l"(v)); return r;
}
// pack two fp32 -> fp16x2 word (v0 in low half)
__device__ __forceinline__ u32 pack_f16(float v0, float v1) {
    __half2 h = __floats2half2_rn(v0, v1);
    return *reinterpret_cast<u32*>(&h);
}
// split pair into fp16 hi word + fp16 lo (residual) word
__device__ __forceinline__ void split_f16(float a0, float a1, u32& hi, u32& lo) {
    __half h0 = __float2half_rn(a0), h1 = __float2half_rn(a1);
    __half2 hh = __halves2half2(h0, h1);
    hi = *reinterpret_cast<u32*>(&hh);
    lo = pack_f16(a0 - __half2float(h0), a1 - __half2float(h1));
}
__device__ __forceinline__ u32 smem_u32(const void* p) {
    u32 a; asm("{ .reg .u64 t; cvta.to.shared.u64 t, %1; cvt.u32.u64 %0, t; }" : "=r"(a) : "l"(p));
    return a;
}
__device__ __forceinline__ void ldsm4(u32 a, u32& r0, u32& r1, u32& r2, u32& r3) {
    asm volatile("ldmatrix.sync.aligned.m8n8.x4.shared.b16 {%0,%1,%2,%3}, [%4];"
                 : "=r"(r0), "=r"(r1), "=r"(r2), "=r"(r3) : "r"(a));
}
__device__ __forceinline__ void mma_f16(float* c, const u32* a, u32 b0, u32 b1) {
    asm volatile(
        "mma.sync.aligned.m16n8k16.row.col.f32.f16.f16.f32 "
        "{%0,%1,%2,%3}, {%4,%5,%6,%7}, {%8,%9}, {%0,%1,%2,%3};"
        : "+f"(c[0]), "+f"(c[1]), "+f"(c[2]), "+f"(c[3])
        : "r"(a[0]), "r"(a[1]), "r"(a[2]), "r"(a[3]), "r"(b0), "r"(b1));
}
__device__ __forceinline__ void cpasync16(u32 dst, const void* src) {
    asm volatile("cp.async.cg.shared.global [%0], [%1], 16;" :: "r"(dst), "l"(src));
}
__device__ __forceinline__ void cp_wait_all() {
    asm volatile("cp.async.commit_group;");
    asm volatile("cp.async.wait_group 0;" ::: "memory");
}

// ==================== fp32 FFMA2 MLP core (node/sender, 256 threads, proven R3) ====================
template <int KIN>
__device__ __forceinline__ void mlp_core(
    float* __restrict__ As, float* __restrict__ A2, float* __restrict__ Bs,
    float* __restrict__ Ys,
    const float* __restrict__ w1, const float* __restrict__ b1,
    const float* __restrict__ w2, const float* __restrict__ b2)
{
    const int tid = threadIdx.x;
    const int tx = tid & 15;
    const int ty = tid >> 4;

    float4* Bs4 = (float4*)Bs;
    const ulonglong2* Bsp = (const ulonglong2*)Bs;

    u64 acc[4][8];
#pragma unroll
    for (int i = 0; i < 4; i++)
#pragma unroll
        for (int j = 0; j < 8; j++) acc[i][j] = 0ull;

    for (int kk = 0; kk < KIN; kk += KC) {
        const float4* wg = (const float4*)(w1 + kk * HN);
#pragma unroll
        for (int t = 0; t < 8; t++) Bs4[tid + t * 256] = wg[tid + t * 256];
        __syncthreads();
#pragma unroll 8
        for (int k = 0; k < KC; k++) {
            u64 a2v[4];
#pragma unroll
            for (int i = 0; i < 4; i++)
                a2v[i] = pack_dup(As[(ty * 4 + i) * KIN + kk + k]);
#pragma unroll
            for (int g = 0; g < 4; g++) {
                ulonglong2 b = Bsp[k * 64 + g * 16 + tx];
#pragma unroll
                for (int i = 0; i < 4; i++) {
                    ffma2(acc[i][g * 2 + 0], a2v[i], b.x);
                    ffma2(acc[i][g * 2 + 1], a2v[i], b.y);
                }
            }
        }
        __syncthreads();
    }

#pragma unroll
    for (int i = 0; i < 4; i++) {
        int r = ty * 4 + i;
#pragma unroll
        for (int g = 0; g < 4; g++) {
            float4 bv = ((const float4*)b1)[g * 16 + tx];
            float2 p0 = unpack2(acc[i][g * 2 + 0]);
            float2 p1 = unpack2(acc[i][g * 2 + 1]);
            float4 h;
            h.x = silu_f(p0.x + bv.x);
            h.y = silu_f(p0.y + bv.y);
            h.z = silu_f(p1.x + bv.z);
            h.w = silu_f(p1.y + bv.w);
            ((float4*)(A2 + r * A2S))[g * 16 + tx] = h;
        }
    }
    __syncthreads();

    u64 acc2[4][4];
#pragma unroll
    for (int i = 0; i < 4; i++)
#pragma unroll
        for (int j = 0; j < 4; j++) acc2[i][j] = 0ull;

    for (int kk = 0; kk < HN; kk += KC) {
        const float4* wg = (const float4*)(w2 + kk * DN);
#pragma unroll
        for (int t = 0; t < 4; t++) Bs4[tid + t * 256] = wg[tid + t * 256];
        __syncthreads();
#pragma unroll 8
        for (int k = 0; k < KC; k++) {
            u64 a2v[4];
#pragma unroll
            for (int i = 0; i < 4; i++)
                a2v[i] = pack_dup(A2[(ty * 4 + i) * A2S + kk + k]);
#pragma unroll
            for (int g = 0; g < 2; g++) {
                ulonglong2 b = Bsp[k * 32 + g * 16 + tx];
#pragma unroll
                for (int i = 0; i < 4; i++) {
                    ffma2(acc2[i][g * 2 + 0], a2v[i], b.x);
                    ffma2(acc2[i][g * 2 + 1], a2v[i], b.y);
                }
            }
        }
        __syncthreads();
    }

#pragma unroll
    for (int i = 0; i < 4; i++) {
        int r = ty * 4 + i;
#pragma unroll
        for (int g = 0; g < 2; g++) {
            float4 bv = ((const float4*)b2)[g * 16 + tx];
            float2 p0 = unpack2(acc2[i][g * 2 + 0]);
            float2 p1 = unpack2(acc2[i][g * 2 + 1]);
            float4 y;
            y.x = p0.x + bv.x;
            y.y = p0.y + bv.y;
            y.z = p1.x + bv.z;
            y.w = p1.y + bv.w;
            ((float4*)(Ys + r * YSS))[g * 16 + tx] = y;
        }
    }
    __syncthreads();
}

__device__ __forceinline__ float4 ln_row(const float* Ys, int rr, int lane,
                                         float4 gm, float4 bt)
{
    float4 v = ((const float4*)(Ys + rr * YSS))[lane];
    float s1 = v.x + v.y + v.z + v.w;
    float s2 = v.x * v.x + v.y * v.y + v.z * v.z + v.w * v.w;
    s1 = warp_reduce_add(s1);
    s2 = warp_reduce_add(s2);
    float mean = s1 * (1.0f / 128.0f);
    float var  = s2 * (1.0f / 128.0f) - mean * mean;
    float rstd = rsqrtf(var + 1e-5f);
    float4 p;
    p.x = (v.x - mean) * rstd * gm.x + bt.x;
    p.y = (v.y - mean) * rstd * gm.y + bt.y;
    p.z = (v.z - mean) * rstd * gm.z + bt.z;
    p.w = (v.w - mean) * rstd * gm.w + bt.w;
    return p;
}

// ------------------------- utility kernels -------------------------
__global__ void detect_idx_kernel(const int* __restrict__ ei)
{
    __shared__ int any;
    if (threadIdx.x == 0) any = 0;
    __syncthreads();
    for (int i = threadIdx.x; i < 2048; i += blockDim.x)
        if (ei[2 * i + 1] != 0) any = 1;
    __syncthreads();
    if (threadIdx.x == 0) g_is64 = (any == 0) ? 1 : 0;
}

__global__ void zero_scratch_kernel()
{
    int i = blockIdx.x * blockDim.x + threadIdx.x;
    int stride = gridDim.x * blockDim.x;
    for (int j = i; j < NNODE * DN; j += stride) g_agg[j] = 0.0f;
    for (int j = i; j < NNODE; j += stride) g_cnt[j] = 0.0f;
}

// Transpose + fp16-convert the edge weights into k-major globals.
__global__ void prep_weights_kernel(const float* __restrict__ ew1,
                                    const float* __restrict__ ew2)
{
    int i = blockIdx.x * blockDim.x + threadIdx.x;
    const int T1 = 256 * 192;
    if (i < T1) {
        int n = i / 192, kp = i % 192;
        float v0 = ew1[(size_t)(2 * kp) * HN + n];
        float v1 = ew1[(size_t)(2 * kp + 1) * HN + n];
        g_w1t[i] = pack_f16(v0, v1);
    } else {
        int i2 = i - T1;
        if (i2 < 128 * 128) {
            int n = i2 / 128, kp = i2 % 128;
            float v0 = ew2[(size_t)(2 * kp) * DN + n];
            float v1 = ew2[(size_t)(2 * kp + 1) * DN + n];
            g_w2t[i2] = pack_f16(v0, v1);
        }
    }
}

// ==================== mma.sync edge kernel (256 thr, 64 rows, 2 CTAs/SM, fp16 2-term) ====================
// smem (bytes):
//  phase1: A1hi [64][136h] @0 (17408)  A1lo @17408  B1 [256][136h] @34816 (69632) end 104448
//  phase2: A2hi [64][264h] @0 (33792)  A2lo @33792  B2half [64][264h] @67584 (33792) end 101376
//  Ys     [64][132 f32] @0 (33792)
#define SA1H 0
#define SA1L 17408
#define SB1  34816
#define SA2H 0
#define SA2L 33792
#define SB2  67584
#define ESMEM 104448
#define ST1  272    // byte stride, GEMM1 tiles (136 halves)
#define ST2  528    // byte stride, GEMM2 tiles (264 halves)

// fused sweep of GEMM1: warp tile m32 x n64, K=128 (8 ksteps), Ahi+Alo vs single B
__device__ __forceinline__ void sweep1f(u32 aHi, u32 aLo, u32 bBase, float (&acc)[2][8][4])
{
#pragma unroll
    for (int ks = 0; ks < 8; ks++) {
        u32 Ah0[4], Ah1[4], Al0[4], Al1[4];
        ldsm4(aHi + ks * 32, Ah0[0], Ah0[1], Ah0[2], Ah0[3]);
        ldsm4(aHi + 16 * ST1 + ks * 32, Ah1[0], Ah1[1], Ah1[2], Ah1[3]);
        ldsm4(aLo + ks * 32, Al0[0], Al0[1], Al0[2], Al0[3]);
        ldsm4(aLo + 16 * ST1 + ks * 32, Al1[0], Al1[1], Al1[2], Al1[3]);
#pragma unroll
        for (int p = 0; p < 4; p++) {
            u32 b0, b1, b2, b3;
            ldsm4(bBase + p * 16 * ST1 + ks * 32, b0, b1, b2, b3);
            mma_f16(acc[0][2 * p + 0], Ah0, b0, b1);
            mma_f16(acc[0][2 * p + 1], Ah0, b2, b3);
            mma_f16(acc[1][2 * p + 0], Ah1, b0, b1);
            mma_f16(acc[1][2 * p + 1], Ah1, b2, b3);
            mma_f16(acc[0][2 * p + 0], Al0, b0, b1);
            mma_f16(acc[0][2 * p + 1], Al0, b2, b3);
            mma_f16(acc[1][2 * p + 0], Al1, b0, b1);
            mma_f16(acc[1][2 * p + 1], Al1, b2, b3);
        }
    }
}

// fused sweep of GEMM2: warp tile m16 x n32, K=256 (16 ksteps)
__device__ __forceinline__ void sweep2f(u32 aHi, u32 aLo, u32 bBase, float (&acc)[4][4])
{
#pragma unroll
    for (int ks = 0; ks < 16; ks++) {
        u32 Ah[4], Al[4];
        ldsm4(aHi + ks * 32, Ah[0], Ah[1], Ah[2], Ah[3]);
        ldsm4(aLo + ks * 32, Al[0], Al[1], Al[2], Al[3]);
#pragma unroll
        for (int p = 0; p < 2; p++) {
            u32 b0, b1, b2, b3;
            ldsm4(bBase + p * 16 * ST2 + ks * 32, b0, b1, b2, b3);
            mma_f16(acc[2 * p + 0], Ah, b0, b1);
            mma_f16(acc[2 * p + 1], Ah, b2, b3);
            mma_f16(acc[2 * p + 0], Al, b0, b1);
            mma_f16(acc[2 * p + 1], Al, b2, b3);
        }
    }
}

__global__ void __launch_bounds__(256, 2)
edge_kernel_mma(const float* __restrict__ sx, const float* __restrict__ rx,
                const float* __restrict__ ea, const int* __restrict__ ei,
                const float* __restrict__ b1, const float* __restrict__ b2,
                const float* __restrict__ gam, const float* __restrict__ bet,
                float* __restrict__ edge_out)
{
    extern __shared__ char smc[];
    const u32 S = smem_u32(smc);

    const int tid = threadIdx.x, lane = tid & 31, warp = tid >> 5;
    const int base = blockIdx.x * EB;
    const int is64 = g_is64;

    const int r8 = lane & 7, q8 = lane >> 3;
    const int g = lane >> 2, tg = lane & 3;

    // ---------------- GEMM1 ----------------
    const int wm = (warp >> 2) * 32;     // 0,32
    const int wn = (warp & 3) * 64;      // 0,64,128,192

    const u32 a1hiA = S + SA1H + (u32)(wm + r8 + (q8 & 1) * 8) * ST1 + (u32)((q8 >> 1) * 8) * 2;
    const u32 a1loA = S + SA1L + (u32)(wm + r8 + (q8 & 1) * 8) * ST1 + (u32)((q8 >> 1) * 8) * 2;
    const u32 b1A   = S + SB1  + (u32)(wn + r8 + (q8 >> 1) * 8) * ST1 + (u32)((q8 & 1) * 8) * 2;

    float acc[2][8][4];
#pragma unroll
    for (int i = 0; i < 2; i++)
#pragma unroll
        for (int j = 0; j < 8; j++)
#pragma unroll
            for (int t = 0; t < 4; t++) acc[i][j][t] = 0.0f;

    // gather source (4 threads per row, 32 cols each)
    const int grow = tid >> 2, gq = tid & 3;
    const int e0 = base + grow;
    const int si = load_idx(ei, e0, is64);
    const int di = load_idx(ei, NEDGE + e0, is64);

    for (int c = 0; c < 3; c++) {
        __syncthreads();   // previous chunk fully consumed

        // stage B1 chunk via cp.async: 256 rows x 16 uint4
        {
            const uint4* gsrc = (const uint4*)g_w1t;
#pragma unroll
            for (int t = 0; t < 16; t++) {
                int idx = tid + t * 256;
                int n = idx >> 4, s = idx & 15;
                cpasync16(S + SB1 + (u32)n * ST1 + (u32)s * 16, gsrc + n * 48 + c * 16 + s);
            }
        }
        // gather + fp16-split A chunk
        {
            const float* src = (c == 0) ? (sx + (size_t)si * DN)
                             : (c == 1) ? (rx + (size_t)di * DN)
                                        : (ea + (size_t)e0 * DN);
#pragma unroll
            for (int it = 0; it < 4; it++) {
                int k0 = gq * 32 + it * 8;
                float4 f0 = ((const float4*)(src + k0))[0];
                float4 f1 = ((const float4*)(src + k0))[1];
                float v[8] = { f0.x, f0.y, f0.z, f0.w, f1.x, f1.y, f1.z, f1.w };
                u32 hw[4], lw[4];
#pragma unroll
                for (int j = 0; j < 4; j++)
                    split_f16(v[2 * j], v[2 * j + 1], hw[j], lw[j]);
                u32 off = (u32)grow * ST1 + (u32)k0 * 2;
                *(uint4*)(smc + SA1H + off) = make_uint4(hw[0], hw[1], hw[2], hw[3]);
                *(uint4*)(smc + SA1L + off) = make_uint4(lw[0], lw[1], lw[2], lw[3]);
            }
        }
        cp_wait_all();
        __syncthreads();

        sweep1f(a1hiA, a1loA, b1A, acc);   // (Ahi + Alo) x B
    }
    __syncthreads();   // all GEMM1 reads done; A2/B2 regions may be written

    // ---------------- epilogue1: bias + SiLU + fp16-split -> A2 ----------------
#pragma unroll
    for (int i = 0; i < 2; i++) {
        int row0 = wm + i * 16 + g;
#pragma unroll
        for (int j = 0; j < 8; j++) {
            int n0 = wn + j * 8 + tg * 2;
            float bv0 = b1[n0], bv1 = b1[n0 + 1];
            float h0 = silu_f(acc[i][j][0] + bv0);
            float h1 = silu_f(acc[i][j][1] + bv1);
            float h2 = silu_f(acc[i][j][2] + bv0);
            float h3 = silu_f(acc[i][j][3] + bv1);
            u32 hiw, low;
            u32 off0 = (u32)row0 * ST2 + (u32)n0 * 2;
            u32 off1 = (u32)(row0 + 8) * ST2 + (u32)n0 * 2;
            split_f16(h0, h1, hiw, low);
            *(u32*)(smc + SA2H + off0) = hiw;
            *(u32*)(smc + SA2L + off0) = low;
            split_f16(h2, h3, hiw, low);
            *(u32*)(smc + SA2H + off1) = hiw;
            *(u32*)(smc + SA2L + off1) = low;
        }
    }

    // ---------------- GEMM2: two 64-col n-halves, single fp16 B ----------------
    const int wm2 = (warp >> 1) * 16;   // 0,16,32,48
    const int wn2 = (warp & 1) * 32;    // 0,32
    const u32 a2hiA = S + SA2H + (u32)(wm2 + r8 + (q8 & 1) * 8) * ST2 + (u32)((q8 >> 1) * 8) * 2;
    const u32 a2loA = S + SA2L + (u32)(wm2 + r8 + (q8 & 1) * 8) * ST2 + (u32)((q8 >> 1) * 8) * 2;
    const u32 b2A   = S + SB2  + (u32)(wn2 + r8 + (q8 >> 1) * 8) * ST2 + (u32)((q8 & 1) * 8) * 2;

    float acc2[2][4][4];
#pragma unroll
    for (int h = 0; h < 2; h++)
#pragma unroll
        for (int j = 0; j < 4; j++)
#pragma unroll
            for (int t = 0; t < 4; t++) acc2[h][j][t] = 0.0f;

    for (int h = 0; h < 2; h++) {
        // stage B2 half: rows h*64..h*64+63, 32 uint4 each
        {
            const uint4* gsrc = (const uint4*)g_w2t;
#pragma unroll
            for (int t = 0; t < 8; t++) {
                int idx = tid + t * 256;
                int n = idx >> 5, s = idx & 31;
                cpasync16(S + SB2 + (u32)n * ST2 + (u32)s * 16, gsrc + (h * 64 + n) * 32 + s);
            }
        }
        cp_wait_all();
        __syncthreads();

        sweep2f(a2hiA, a2loA, b2A, acc2[h]);
        __syncthreads();
    }

    // ---------------- epilogue2a: bias -> Ys fp32 (aliases A2hi region) ----------------
#pragma unroll
    for (int h = 0; h < 2; h++) {
        int row0 = wm2 + g;
#pragma unroll
        for (int j = 0; j < 4; j++) {
            int n0 = h * 64 + wn2 + j * 8 + tg * 2;
            float bv0 = b2[n0], bv1 = b2[n0 + 1];
            float2 y0 = make_float2(acc2[h][j][0] + bv0, acc2[h][j][1] + bv1);
            float2 y1 = make_float2(acc2[h][j][2] + bv0, acc2[h][j][3] + bv1);
            *(float2*)(smc + (u32)row0 * ST2 + (u32)n0 * 4)       = y0;
            *(float2*)(smc + (u32)(row0 + 8) * ST2 + (u32)n0 * 4) = y1;
        }
    }
    __syncthreads();

    // ---------------- epilogue2b: LN + residual + atomic scatter ----------------
    {
        const float* Ys = (const float*)smc;
        float4 gm = ((const float4*)gam)[lane];
        float4 bt = ((const float4*)bet)[lane];
#pragma unroll 1
        for (int it = 0; it < 8; it++) {
            int rr = warp * 8 + it;
            int e = base + rr;
            float4 p = ln_row(Ys, rr, lane, gm, bt);
            int d = load_idx(ei, NEDGE + e, is64);
            float4 ev = ((const float4*)(ea + (size_t)e * DN))[lane];
            float4 o;
            o.x = ev.x + p.x; o.y = ev.y + p.y; o.z = ev.z + p.z; o.w = ev.w + p.w;
            ((float4*)(edge_out + (size_t)e * DN))[lane] = o;
            float* ag = g_agg + (size_t)d * DN + lane * 4;
            atomicAdd(ag + 0, p.x);
            atomicAdd(ag + 1, p.y);
            atomicAdd(ag + 2, p.z);
            atomicAdd(ag + 3, p.w);
            if (lane == 0) atomicAdd(&g_cnt[d], 1.0f);
        }
    }
}

// ==================== node / sender (proven R3) ====================
__global__ void __launch_bounds__(256, 1)
node_kernel(const float* __restrict__ rx,
            const float* __restrict__ w1, const float* __restrict__ b1,
            const float* __restrict__ w2, const float* __restrict__ b2,
            const float* __restrict__ gam, const float* __restrict__ bet,
            float* __restrict__ recv_out)
{
    extern __shared__ float smem[];
    float* As = smem;
    float* A2 = As + TM * 256;
    float* Bs = A2 + TM * A2S;
    float* Ys = As;

    const int tid = threadIdx.x, lane = tid & 31, warp = tid >> 5;
    const int base = blockIdx.x * TM;

#pragma unroll
    for (int it = 0; it < 8; it++) {
        int nl = warp * 8 + it;
        int n = base + nl;
        ((float4*)(As + nl * 256))[lane] = ((const float4*)(rx + (size_t)n * DN))[lane];
        float c = g_cnt[n];
        float inv = 1.0f / fmaxf(c, 1.0f);
        float4 a = ((const float4*)(g_agg + (size_t)n * DN))[lane];
        a.x *= inv; a.y *= inv; a.z *= inv; a.w *= inv;
        ((float4*)(As + nl * 256 + 128))[lane] = a;
    }
    __syncthreads();

    mlp_core<256>(As, A2, Bs, Ys, w1, b1, w2, b2);

    float4 gm = ((const float4*)gam)[lane];
    float4 bt = ((const float4*)bet)[lane];
#pragma unroll 1
    for (int it = 0; it < 8; it++) {
        int rr = warp * 8 + it;
        int n = base + rr;
        float4 p = ln_row(Ys, rr, lane, gm, bt);
        float4 xv = ((const float4*)(rx + (size_t)n * DN))[lane];
        float4 o;
        o.x = xv.x + p.x; o.y = xv.y + p.y; o.z = xv.z + p.z; o.w = xv.w + p.w;
        ((float4*)(recv_out + (size_t)n * DN))[lane] = o;
    }
}

__global__ void __launch_bounds__(256, 1)
sender_kernel(const float* __restrict__ sx,
              const float* __restrict__ w1, const float* __restrict__ b1,
              const float* __restrict__ w2, const float* __restrict__ b2,
              const float* __restrict__ gam, const float* __restrict__ bet,
              float* __restrict__ send_out)
{
    extern __shared__ float smem[];
    float* As = smem;
    float* A2 = smem + TM * YSS;
    float* Bs = A2 + TM * A2S;
    float* Ys = As;

    const int tid = threadIdx.x, lane = tid & 31, warp = tid >> 5;
    const int base = blockIdx.x * TM;

#pragma unroll
    for (int it = 0; it < 8; it++) {
        int nl = warp * 8 + it;
        int n = base + nl;
        ((float4*)(As + nl * 128))[lane] = ((const float4*)(sx + (size_t)n * DN))[lane];
    }
    __syncthreads();

    mlp_core<128>(As, A2, Bs, Ys, w1, b1, w2, b2);

    float4 gm = ((const float4*)gam)[lane];
    float4 bt = ((const float4*)bet)[lane];
#pragma unroll 1
    for (int it = 0; it < 8; it++) {
        int rr = warp * 8 + it;
        int n = base + rr;
        float4 p = ln_row(Ys, rr, lane, gm, bt);
        float4 xv = ((const float4*)(sx + (size_t)n * DN))[lane];
        float4 o;
        o.x = xv.x + p.x; o.y = xv.y + p.y; o.z = xv.z + p.z; o.w = xv.w + p.w;
        ((float4*)(send_out + (size_t)n * DN))[lane] = o;
    }
}

// ------------------------- launch -------------------------
extern "C" void kernel_launch(void* const* d_in, const int* in_sizes, int n_in,
                              void* d_out, int out_size)
{
    const float* sx    = (const float*)d_in[0];
    const float* rx    = (const float*)d_in[1];
    const float* ea    = (const float*)d_in[2];
    const int*   ei    = (const int*)d_in[3];
    const float* ew1   = (const float*)d_in[4];
    const float* eb1   = (const float*)d_in[5];
    const float* ew2   = (const float*)d_in[6];
    const float* eb2   = (const float*)d_in[7];
    const float* eg    = (const float*)d_in[8];
    const float* ebeta = (const float*)d_in[9];
    const float* nw1   = (const float*)d_in[10];
    const float* nb1   = (const float*)d_in[11];
    const float* nw2   = (const float*)d_in[12];
    const float* nb2   = (const float*)d_in[13];
    const float* ng    = (const float*)d_in[14];
    const float* nbeta = (const float*)d_in[15];
    const float* sw1   = (const float*)d_in[16];
    const float* sb1   = (const float*)d_in[17];
    const float* sw2   = (const float*)d_in[18];
    const float* sb2   = (const float*)d_in[19];
    const float* sg    = (const float*)d_in[20];
    const float* sbeta = (const float*)d_in[21];

    float* out = (float*)d_out;
    float* send_out = out;
    float* recv_out = out + (size_t)NNODE * DN;
    float* edge_out = out + (size_t)2 * NNODE * DN;

    const int smemN = (TM * 256 + TM * A2S + KC * HN) * (int)sizeof(float);
    const int smemS = (TM * YSS + TM * A2S + KC * HN) * (int)sizeof(float);
    cudaFuncSetAttribute(edge_kernel_mma, cudaFuncAttributeMaxDynamicSharedMemorySize, ESMEM);
    cudaFuncSetAttribute(node_kernel,     cudaFuncAttributeMaxDynamicSharedMemorySize, smemN);
    cudaFuncSetAttribute(sender_kernel,   cudaFuncAttributeMaxDynamicSharedMemorySize, smemS);

    detect_idx_kernel<<<1, 256>>>(ei);
    prep_weights_kernel<<<256, 256>>>(ew1, ew2);
    zero_scratch_kernel<<<296, 256>>>();

    edge_kernel_mma<<<NEDGE / EB, 256, ESMEM>>>(
        sx, rx, ea, ei, eb1, eb2, eg, ebeta, edge_out);

    sender_kernel<<<NNODE / TM, 256, smemS>>>(
        sx, sw1, sb1, sw2, sb2, sg, sbeta, send_out);

    node_kernel<<<NNODE / TM, 256, smemN>>>(
        rx, nw1, nb1, nw2, nb2, ng, nbeta, recv_out);
}

// round 15
// speedup vs baseline: 4.2546x; 1.7886x over previous
#include <cuda_runtime.h>
#include <cuda_bf16.h>
#include <cuda_fp16.h>
#include <math.h>

// Problem constants
#define DN     128
#define HN     256
#define NNODE  40000
#define NEDGE  640000
#define TM     64       // row tile for fp32 node/sender kernels
#define A2S    260
#define YSS    132
#define KC     32
#define EB     64       // edge rows per CTA (mma kernel)

typedef unsigned long long u64;
typedef unsigned int u32;

// ------------------------- device globals (no allocation allowed) -------------------------
__device__ float g_agg[NNODE * DN];
__device__ float g_cnt[NNODE];
__device__ int   g_is64;

// Pre-transposed fp16 edge weights (written by prep kernel each launch)
// W1T: [256 n][384 k] fp16, k-major.  u32 index = n*192 + k/2
__device__ u32 g_w1t[256 * 192];
// W2T: [128 n][256 k] fp16, k-major.  u32 index = n*128 + k/2
__device__ u32 g_w2t[128 * 128];

// ------------------------- helpers -------------------------
__device__ __forceinline__ float silu_f(float x) {
    return x * (1.0f / (1.0f + __expf(-x)));
}
__device__ __forceinline__ float warp_reduce_add(float v) {
#pragma unroll
    for (int o = 16; o > 0; o >>= 1) v += __shfl_xor_sync(0xffffffffu, v, o);
    return v;
}
__device__ __forceinline__ int load_idx(const int* __restrict__ ei, int pos, int is64) {
    return is64 ? ei[2 * pos] : ei[pos];
}
__device__ __forceinline__ void ffma2(u64& d, u64 a, u64 b) {
    asm("fma.rn.f32x2 %0, %1, %2, %0;" : "+l"(d) : "l"(a), "l"(b));
}
__device__ __forceinline__ u64 pack_dup(float a) {
    u64 r; asm("mov.b64 %0, {%1, %1};" : "=l"(r) : "f"(a)); return r;
}
__device__ __forceinline__ float2 unpack2(u64 v) {
    float2 r; asm("mov.b64 {%0, %1}, %2;" : "=f"(r.x), "=f"(r.y) : "l"(v)); return r;
}
// pack two fp32 -> fp16x2 word (v0 in low half)
__device__ __forceinline__ u32 pack_f16(float v0, float v1) {
    __half2 h = __floats2half2_rn(v0, v1);
    return *reinterpret_cast<u32*>(&h);
}
__device__ __forceinline__ u32 smem_u32(const void* p) {
    u32 a; asm("{ .reg .u64 t; cvta.to.shared.u64 t, %1; cvt.u32.u64 %0, t; }" : "=r"(a) : "l"(p));
    return a;
}
__device__ __forceinline__ void ldsm4(u32 a, u32& r0, u32& r1, u32& r2, u32& r3) {
    asm volatile("ldmatrix.sync.aligned.m8n8.x4.shared.b16 {%0,%1,%2,%3}, [%4];"
                 : "=r"(r0), "=r"(r1), "=r"(r2), "=r"(r3) : "r"(a));
}
__device__ __forceinline__ void mma_f16(float* c, const u32* a, u32 b0, u32 b1) {
    asm volatile(
        "mma.sync.aligned.m16n8k16.row.col.f32.f16.f16.f32 "
        "{%0,%1,%2,%3}, {%4,%5,%6,%7}, {%8,%9}, {%0,%1,%2,%3};"
        : "+f"(c[0]), "+f"(c[1]), "+f"(c[2]), "+f"(c[3])
        : "r"(a[0]), "r"(a[1]), "r"(a[2]), "r"(a[3]), "r"(b0), "r"(b1));
}
__device__ __forceinline__ void cpasync16(u32 dst, const void* src) {
    asm volatile("cp.async.cg.shared.global [%0], [%1], 16;" :: "r"(dst), "l"(src));
}
__device__ __forceinline__ void cp_wait_all() {
    asm volatile("cp.async.commit_group;");
    asm volatile("cp.async.wait_group 0;" ::: "memory");
}

// ==================== fp32 FFMA2 MLP core (node/sender, 256 threads, proven R3) ====================
template <int KIN>
__device__ __forceinline__ void mlp_core(
    float* __restrict__ As, float* __restrict__ A2, float* __restrict__ Bs,
    float* __restrict__ Ys,
    const float* __restrict__ w1, const float* __restrict__ b1,
    const float* __restrict__ w2, const float* __restrict__ b2)
{
    const int tid = threadIdx.x;
    const int tx = tid & 15;
    const int ty = tid >> 4;

    float4* Bs4 = (float4*)Bs;
    const ulonglong2* Bsp = (const ulonglong2*)Bs;

    u64 acc[4][8];
#pragma unroll
    for (int i = 0; i < 4; i++)
#pragma unroll
        for (int j = 0; j < 8; j++) acc[i][j] = 0ull;

    for (int kk = 0; kk < KIN; kk += KC) {
        const float4* wg = (const float4*)(w1 + kk * HN);
#pragma unroll
        for (int t = 0; t < 8; t++) Bs4[tid + t * 256] = wg[tid + t * 256];
        __syncthreads();
#pragma unroll 8
        for (int k = 0; k < KC; k++) {
            u64 a2v[4];
#pragma unroll
            for (int i = 0; i < 4; i++)
                a2v[i] = pack_dup(As[(ty * 4 + i) * KIN + kk + k]);
#pragma unroll
            for (int g = 0; g < 4; g++) {
                ulonglong2 b = Bsp[k * 64 + g * 16 + tx];
#pragma unroll
                for (int i = 0; i < 4; i++) {
                    ffma2(acc[i][g * 2 + 0], a2v[i], b.x);
                    ffma2(acc[i][g * 2 + 1], a2v[i], b.y);
                }
            }
        }
        __syncthreads();
    }

#pragma unroll
    for (int i = 0; i < 4; i++) {
        int r = ty * 4 + i;
#pragma unroll
        for (int g = 0; g < 4; g++) {
            float4 bv = ((const float4*)b1)[g * 16 + tx];
            float2 p0 = unpack2(acc[i][g * 2 + 0]);
            float2 p1 = unpack2(acc[i][g * 2 + 1]);
            float4 h;
            h.x = silu_f(p0.x + bv.x);
            h.y = silu_f(p0.y + bv.y);
            h.z = silu_f(p1.x + bv.z);
            h.w = silu_f(p1.y + bv.w);
            ((float4*)(A2 + r * A2S))[g * 16 + tx] = h;
        }
    }
    __syncthreads();

    u64 acc2[4][4];
#pragma unroll
    for (int i = 0; i < 4; i++)
#pragma unroll
        for (int j = 0; j < 4; j++) acc2[i][j] = 0ull;

    for (int kk = 0; kk < HN; kk += KC) {
        const float4* wg = (const float4*)(w2 + kk * DN);
#pragma unroll
        for (int t = 0; t < 4; t++) Bs4[tid + t * 256] = wg[tid + t * 256];
        __syncthreads();
#pragma unroll 8
        for (int k = 0; k < KC; k++) {
            u64 a2v[4];
#pragma unroll
            for (int i = 0; i < 4; i++)
                a2v[i] = pack_dup(A2[(ty * 4 + i) * A2S + kk + k]);
#pragma unroll
            for (int g = 0; g < 2; g++) {
                ulonglong2 b = Bsp[k * 32 + g * 16 + tx];
#pragma unroll
                for (int i = 0; i < 4; i++) {
                    ffma2(acc2[i][g * 2 + 0], a2v[i], b.x);
                    ffma2(acc2[i][g * 2 + 1], a2v[i], b.y);
                }
            }
        }
        __syncthreads();
    }

#pragma unroll
    for (int i = 0; i < 4; i++) {
        int r = ty * 4 + i;
#pragma unroll
        for (int g = 0; g < 2; g++) {
            float4 bv = ((const float4*)b2)[g * 16 + tx];
            float2 p0 = unpack2(acc2[i][g * 2 + 0]);
            float2 p1 = unpack2(acc2[i][g * 2 + 1]);
            float4 y;
            y.x = p0.x + bv.x;
            y.y = p0.y + bv.y;
            y.z = p1.x + bv.z;
            y.w = p1.y + bv.w;
            ((float4*)(Ys + r * YSS))[g * 16 + tx] = y;
        }
    }
    __syncthreads();
}

__device__ __forceinline__ float4 ln_row(const float* Ys, int rr, int lane,
                                         float4 gm, float4 bt)
{
    float4 v = ((const float4*)(Ys + rr * YSS))[lane];
    float s1 = v.x + v.y + v.z + v.w;
    float s2 = v.x * v.x + v.y * v.y + v.z * v.z + v.w * v.w;
    s1 = warp_reduce_add(s1);
    s2 = warp_reduce_add(s2);
    float mean = s1 * (1.0f / 128.0f);
    float var  = s2 * (1.0f / 128.0f) - mean * mean;
    float rstd = rsqrtf(var + 1e-5f);
    float4 p;
    p.x = (v.x - mean) * rstd * gm.x + bt.x;
    p.y = (v.y - mean) * rstd * gm.y + bt.y;
    p.z = (v.z - mean) * rstd * gm.z + bt.z;
    p.w = (v.w - mean) * rstd * gm.w + bt.w;
    return p;
}

// ------------------------- utility kernels -------------------------
__global__ void detect_idx_kernel(const int* __restrict__ ei)
{
    __shared__ int any;
    if (threadIdx.x == 0) any = 0;
    __syncthreads();
    for (int i = threadIdx.x; i < 2048; i += blockDim.x)
        if (ei[2 * i + 1] != 0) any = 1;
    __syncthreads();
    if (threadIdx.x == 0) g_is64 = (any == 0) ? 1 : 0;
}

__global__ void zero_scratch_kernel()
{
    int i = blockIdx.x * blockDim.x + threadIdx.x;
    int stride = gridDim.x * blockDim.x;
    for (int j = i; j < NNODE * DN; j += stride) g_agg[j] = 0.0f;
    for (int j = i; j < NNODE; j += stride) g_cnt[j] = 0.0f;
}

// Transpose + fp16-convert the edge weights into k-major globals.
__global__ void prep_weights_kernel(const float* __restrict__ ew1,
                                    const float* __restrict__ ew2)
{
    int i = blockIdx.x * blockDim.x + threadIdx.x;
    const int T1 = 256 * 192;
    if (i < T1) {
        int n = i / 192, kp = i % 192;
        float v0 = ew1[(size_t)(2 * kp) * HN + n];
        float v1 = ew1[(size_t)(2 * kp + 1) * HN + n];
        g_w1t[i] = pack_f16(v0, v1);
    } else {
        int i2 = i - T1;
        if (i2 < 128 * 128) {
            int n = i2 / 128, kp = i2 % 128;
            float v0 = ew2[(size_t)(2 * kp) * DN + n];
            float v1 = ew2[(size_t)(2 * kp + 1) * DN + n];
            g_w2t[i2] = pack_f16(v0, v1);
        }
    }
}

// ==================== mma.sync edge kernel (256 thr, 64 rows, 2 CTAs/SM, pure fp16) ====================
// smem (bytes):
//  phase1: A1 [64][136h] @0 (17408)  B1 [256][136h] @17408 (69632) end 87040
//  phase2: A2 [64][264h] @0 (33792)  B2half [64][264h] @33792 (33792) end 67584
//  Ys     [64][132 f32] @0 (33792)
#define SA1  0
#define SB1  17408
#define SA2  0
#define SB2  33792
#define ESMEM 87040
#define ST1  272    // byte stride, GEMM1 tiles (136 halves)
#define ST2  528    // byte stride, GEMM2 tiles (264 halves)

// sweep of GEMM1: warp tile m32 x n64, K=128 (8 ksteps), single fp16 A x B
__device__ __forceinline__ void sweep1(u32 aBase, u32 bBase, float (&acc)[2][8][4])
{
#pragma unroll
    for (int ks = 0; ks < 8; ks++) {
        u32 A0[4], A1[4];
        ldsm4(aBase + ks * 32, A0[0], A0[1], A0[2], A0[3]);
        ldsm4(aBase + 16 * ST1 + ks * 32, A1[0], A1[1], A1[2], A1[3]);
#pragma unroll
        for (int p = 0; p < 4; p++) {
            u32 b0, b1, b2, b3;
            ldsm4(bBase + p * 16 * ST1 + ks * 32, b0, b1, b2, b3);
            mma_f16(acc[0][2 * p + 0], A0, b0, b1);
            mma_f16(acc[0][2 * p + 1], A0, b2, b3);
            mma_f16(acc[1][2 * p + 0], A1, b0, b1);
            mma_f16(acc[1][2 * p + 1], A1, b2, b3);
        }
    }
}

// sweep of GEMM2: warp tile m16 x n32, K=256 (16 ksteps)
__device__ __forceinline__ void sweep2(u32 aBase, u32 bBase, float (&acc)[4][4])
{
#pragma unroll
    for (int ks = 0; ks < 16; ks++) {
        u32 A0[4];
        ldsm4(aBase + ks * 32, A0[0], A0[1], A0[2], A0[3]);
#pragma unroll
        for (int p = 0; p < 2; p++) {
            u32 b0, b1, b2, b3;
            ldsm4(bBase + p * 16 * ST2 + ks * 32, b0, b1, b2, b3);
            mma_f16(acc[2 * p + 0], A0, b0, b1);
            mma_f16(acc[2 * p + 1], A0, b2, b3);
        }
    }
}

__global__ void __launch_bounds__(256, 2)
edge_kernel_mma(const float* __restrict__ sx, const float* __restrict__ rx,
                const float* __restrict__ ea, const int* __restrict__ ei,
                const float* __restrict__ b1, const float* __restrict__ b2,
                const float* __restrict__ gam, const float* __restrict__ bet,
                float* __restrict__ edge_out)
{
    extern __shared__ char smc[];
    const u32 S = smem_u32(smc);

    const int tid = threadIdx.x, lane = tid & 31, warp = tid >> 5;
    const int base = blockIdx.x * EB;
    const int is64 = g_is64;

    const int r8 = lane & 7, q8 = lane >> 3;
    const int g = lane >> 2, tg = lane & 3;

    // ---------------- GEMM1 ----------------
    const int wm = (warp >> 2) * 32;     // 0,32
    const int wn = (warp & 3) * 64;      // 0,64,128,192

    const u32 a1A = S + SA1 + (u32)(wm + r8 + (q8 & 1) * 8) * ST1 + (u32)((q8 >> 1) * 8) * 2;
    const u32 b1A = S + SB1 + (u32)(wn + r8 + (q8 >> 1) * 8) * ST1 + (u32)((q8 & 1) * 8) * 2;

    float acc[2][8][4];
#pragma unroll
    for (int i = 0; i < 2; i++)
#pragma unroll
        for (int j = 0; j < 8; j++)
#pragma unroll
            for (int t = 0; t < 4; t++) acc[i][j][t] = 0.0f;

    // gather source (4 threads per row, 32 cols each)
    const int grow = tid >> 2, gq = tid & 3;
    const int e0 = base + grow;
    const int si = load_idx(ei, e0, is64);
    const int di = load_idx(ei, NEDGE + e0, is64);

    for (int c = 0; c < 3; c++) {
        __syncthreads();   // previous chunk fully consumed

        // stage B1 chunk via cp.async: 256 rows x 16 uint4
        {
            const uint4* gsrc = (const uint4*)g_w1t;
#pragma unroll
            for (int t = 0; t < 16; t++) {
                int idx = tid + t * 256;
                int n = idx >> 4, s = idx & 15;
                cpasync16(S + SB1 + (u32)n * ST1 + (u32)s * 16, gsrc + n * 48 + c * 16 + s);
            }
        }
        // gather + fp16-convert A chunk
        {
            const float* src = (c == 0) ? (sx + (size_t)si * DN)
                             : (c == 1) ? (rx + (size_t)di * DN)
                                        : (ea + (size_t)e0 * DN);
#pragma unroll
            for (int it = 0; it < 4; it++) {
                int k0 = gq * 32 + it * 8;
                float4 f0 = ((const float4*)(src + k0))[0];
                float4 f1 = ((const float4*)(src + k0))[1];
                u32 hw[4];
                hw[0] = pack_f16(f0.x, f0.y);
                hw[1] = pack_f16(f0.z, f0.w);
                hw[2] = pack_f16(f1.x, f1.y);
                hw[3] = pack_f16(f1.z, f1.w);
                u32 off = (u32)grow * ST1 + (u32)k0 * 2;
                *(uint4*)(smc + SA1 + off) = make_uint4(hw[0], hw[1], hw[2], hw[3]);
            }
        }
        cp_wait_all();
        __syncthreads();

        sweep1(a1A, b1A, acc);
    }
    __syncthreads();   // all GEMM1 reads done; A2/B2 regions may be written

    // ---------------- epilogue1: bias + SiLU + fp16 -> A2 ----------------
#pragma unroll
    for (int i = 0; i < 2; i++) {
        int row0 = wm + i * 16 + g;
#pragma unroll
        for (int j = 0; j < 8; j++) {
            int n0 = wn + j * 8 + tg * 2;
            float bv0 = b1[n0], bv1 = b1[n0 + 1];
            float h0 = silu_f(acc[i][j][0] + bv0);
            float h1 = silu_f(acc[i][j][1] + bv1);
            float h2 = silu_f(acc[i][j][2] + bv0);
            float h3 = silu_f(acc[i][j][3] + bv1);
            u32 off0 = (u32)row0 * ST2 + (u32)n0 * 2;
            u32 off1 = (u32)(row0 + 8) * ST2 + (u32)n0 * 2;
            *(u32*)(smc + SA2 + off0) = pack_f16(h0, h1);
            *(u32*)(smc + SA2 + off1) = pack_f16(h2, h3);
        }
    }

    // ---------------- GEMM2: two 64-col n-halves ----------------
    const int wm2 = (warp >> 1) * 16;   // 0,16,32,48
    const int wn2 = (warp & 1) * 32;    // 0,32
    const u32 a2A = S + SA2 + (u32)(wm2 + r8 + (q8 & 1) * 8) * ST2 + (u32)((q8 >> 1) * 8) * 2;
    const u32 b2A = S + SB2 + (u32)(wn2 + r8 + (q8 >> 1) * 8) * ST2 + (u32)((q8 & 1) * 8) * 2;

    float acc2[2][4][4];
#pragma unroll
    for (int h = 0; h < 2; h++)
#pragma unroll
        for (int j = 0; j < 4; j++)
#pragma unroll
            for (int t = 0; t < 4; t++) acc2[h][j][t] = 0.0f;

    for (int h = 0; h < 2; h++) {
        // stage B2 half: rows h*64..h*64+63, 32 uint4 each
        {
            const uint4* gsrc = (const uint4*)g_w2t;
#pragma unroll
            for (int t = 0; t < 8; t++) {
                int idx = tid + t * 256;
                int n = idx >> 5, s = idx & 31;
                cpasync16(S + SB2 + (u32)n * ST2 + (u32)s * 16, gsrc + (h * 64 + n) * 32 + s);
            }
        }
        cp_wait_all();
        __syncthreads();

        sweep2(a2A, b2A, acc2[h]);
        __syncthreads();
    }

    // ---------------- epilogue2a: bias -> Ys fp32 (aliases A2 region) ----------------
#pragma unroll
    for (int h = 0; h < 2; h++) {
        int row0 = wm2 + g;
#pragma unroll
        for (int j = 0; j < 4; j++) {
            int n0 = h * 64 + wn2 + j * 8 + tg * 2;
            float bv0 = b2[n0], bv1 = b2[n0 + 1];
            float2 y0 = make_float2(acc2[h][j][0] + bv0, acc2[h][j][1] + bv1);
            float2 y1 = make_float2(acc2[h][j][2] + bv0, acc2[h][j][3] + bv1);
            *(float2*)(smc + (u32)row0 * ST2 + (u32)n0 * 4)       = y0;
            *(float2*)(smc + (u32)(row0 + 8) * ST2 + (u32)n0 * 4) = y1;
        }
    }
    __syncthreads();

    // ---------------- epilogue2b: LN + residual + atomic scatter ----------------
    {
        const float* Ys = (const float*)smc;
        float4 gm = ((const float4*)gam)[lane];
        float4 bt = ((const float4*)bet)[lane];
#pragma unroll 1
        for (int it = 0; it < 8; it++) {
            int rr = warp * 8 + it;
            int e = base + rr;
            float4 p = ln_row(Ys, rr, lane, gm, bt);
            int d = load_idx(ei, NEDGE + e, is64);
            float4 ev = ((const float4*)(ea + (size_t)e * DN))[lane];
            float4 o;
            o.x = ev.x + p.x; o.y = ev.y + p.y; o.z = ev.z + p.z; o.w = ev.w + p.w;
            ((float4*)(edge_out + (size_t)e * DN))[lane] = o;
            float* ag = g_agg + (size_t)d * DN + lane * 4;
            atomicAdd(ag + 0, p.x);
            atomicAdd(ag + 1, p.y);
            atomicAdd(ag + 2, p.z);
            atomicAdd(ag + 3, p.w);
            if (lane == 0) atomicAdd(&g_cnt[d], 1.0f);
        }
    }
}

// ==================== node / sender (proven R3) ====================
__global__ void __launch_bounds__(256, 1)
node_kernel(const float* __restrict__ rx,
            const float* __restrict__ w1, const float* __restrict__ b1,
            const float* __restrict__ w2, const float* __restrict__ b2,
            const float* __restrict__ gam, const float* __restrict__ bet,
            float* __restrict__ recv_out)
{
    extern __shared__ float smem[];
    float* As = smem;
    float* A2 = As + TM * 256;
    float* Bs = A2 + TM * A2S;
    float* Ys = As;

    const int tid = threadIdx.x, lane = tid & 31, warp = tid >> 5;
    const int base = blockIdx.x * TM;

#pragma unroll
    for (int it = 0; it < 8; it++) {
        int nl = warp * 8 + it;
        int n = base + nl;
        ((float4*)(As + nl * 256))[lane] = ((const float4*)(rx + (size_t)n * DN))[lane];
        float c = g_cnt[n];
        float inv = 1.0f / fmaxf(c, 1.0f);
        float4 a = ((const float4*)(g_agg + (size_t)n * DN))[lane];
        a.x *= inv; a.y *= inv; a.z *= inv; a.w *= inv;
        ((float4*)(As + nl * 256 + 128))[lane] = a;
    }
    __syncthreads();

    mlp_core<256>(As, A2, Bs, Ys, w1, b1, w2, b2);

    float4 gm = ((const float4*)gam)[lane];
    float4 bt = ((const float4*)bet)[lane];
#pragma unroll 1
    for (int it = 0; it < 8; it++) {
        int rr = warp * 8 + it;
        int n = base + rr;
        float4 p = ln_row(Ys, rr, lane, gm, bt);
        float4 xv = ((const float4*)(rx + (size_t)n * DN))[lane];
        float4 o;
        o.x = xv.x + p.x; o.y = xv.y + p.y; o.z = xv.z + p.z; o.w = xv.w + p.w;
        ((float4*)(recv_out + (size_t)n * DN))[lane] = o;
    }
}

__global__ void __launch_bounds__(256, 1)
sender_kernel(const float* __restrict__ sx,
              const float* __restrict__ w1, const float* __restrict__ b1,
              const float* __restrict__ w2, const float* __restrict__ b2,
              const float* __restrict__ gam, const float* __restrict__ bet,
              float* __restrict__ send_out)
{
    extern __shared__ float smem[];
    float* As = smem;
    float* A2 = smem + TM * YSS;
    float* Bs = A2 + TM * A2S;
    float* Ys = As;

    const int tid = threadIdx.x, lane = tid & 31, warp = tid >> 5;
    const int base = blockIdx.x * TM;

#pragma unroll
    for (int it = 0; it < 8; it++) {
        int nl = warp * 8 + it;
        int n = base + nl;
        ((float4*)(As + nl * 128))[lane] = ((const float4*)(sx + (size_t)n * DN))[lane];
    }
    __syncthreads();

    mlp_core<128>(As, A2, Bs, Ys, w1, b1, w2, b2);

    float4 gm = ((const float4*)gam)[lane];
    float4 bt = ((const float4*)bet)[lane];
#pragma unroll 1
    for (int it = 0; it < 8; it++) {
        int rr = warp * 8 + it;
        int n = base + rr;
        float4 p = ln_row(Ys, rr, lane, gm, bt);
        float4 xv = ((const float4*)(sx + (size_t)n * DN))[lane];
        float4 o;
        o.x = xv.x + p.x; o.y = xv.y + p.y; o.z = xv.z + p.z; o.w = xv.w + p.w;
        ((float4*)(send_out + (size_t)n * DN))[lane] = o;
    }
}

// ------------------------- launch -------------------------
extern "C" void kernel_launch(void* const* d_in, const int* in_sizes, int n_in,
                              void* d_out, int out_size)
{
    const float* sx    = (const float*)d_in[0];
    const float* rx    = (const float*)d_in[1];
    const float* ea    = (const float*)d_in[2];
    const int*   ei    = (const int*)d_in[3];
    const float* ew1   = (const float*)d_in[4];
    const float* eb1   = (const float*)d_in[5];
    const float* ew2   = (const float*)d_in[6];
    const float* eb2   = (const float*)d_in[7];
    const float* eg    = (const float*)d_in[8];
    const float* ebeta = (const float*)d_in[9];
    const float* nw1   = (const float*)d_in[10];
    const float* nb1   = (const float*)d_in[11];
    const float* nw2   = (const float*)d_in[12];
    const float* nb2   = (const float*)d_in[13];
    const float* ng    = (const float*)d_in[14];
    const float* nbeta = (const float*)d_in[15];
    const float* sw1   = (const float*)d_in[16];
    const float* sb1   = (const float*)d_in[17];
    const float* sw2   = (const float*)d_in[18];
    const float* sb2   = (const float*)d_in[19];
    const float* sg    = (const float*)d_in[20];
    const float* sbeta = (const float*)d_in[21];

    float* out = (float*)d_out;
    float* send_out = out;
    float* recv_out = out + (size_t)NNODE * DN;
    float* edge_out = out + (size_t)2 * NNODE * DN;

    const int smemN = (TM * 256 + TM * A2S + KC * HN) * (int)sizeof(float);
    const int smemS = (TM * YSS + TM * A2S + KC * HN) * (int)sizeof(float);
    cudaFuncSetAttribute(edge_kernel_mma, cudaFuncAttributeMaxDynamicSharedMemorySize, ESMEM);
    cudaFuncSetAttribute(node_kernel,     cudaFuncAttributeMaxDynamicSharedMemorySize, smemN);
    cudaFuncSetAttribute(sender_kernel,   cudaFuncAttributeMaxDynamicSharedMemorySize, smemS);

    detect_idx_kernel<<<1, 256>>>(ei);
    prep_weights_kernel<<<256, 256>>>(ew1, ew2);
    zero_scratch_kernel<<<296, 256>>>();

    edge_kernel_mma<<<NEDGE / EB, 256, ESMEM>>>(
        sx, rx, ea, ei, eb1, eb2, eg, ebeta, edge_out);

    sender_kernel<<<NNODE / TM, 256, smemS>>>(
        sx, sw1, sb1, sw2, sb2, sg, sbeta, send_out);

    node_kernel<<<NNODE / TM, 256, smemN>>>(
        rx, nw1, nb1, nw2, nb2, ng, nbeta, recv_out);
}

// round 16
// speedup vs baseline: 5.4589x; 1.2830x over previous
#include <cuda_runtime.h>
#include <cuda_bf16.h>
#include <cuda_fp16.h>
#include <math.h>

// Problem constants
#define DN     128
#define HN     256
#define NNODE  40000
#define NEDGE  640000
#define EB     64       // rows per CTA (all mma kernels)

typedef unsigned long long u64;
typedef unsigned int u32;

// ------------------------- device globals (no allocation allowed) -------------------------
__device__ float g_agg[NNODE * DN];
__device__ float g_cnt[NNODE];
__device__ int   g_is64;

// Pre-transposed fp16 weights (written by prep kernel each launch), all k-major
__device__ u32 g_w1t[256 * 192];   // edge W1: [256 n][384 k]
__device__ u32 g_w2t[128 * 128];   // edge W2: [128 n][256 k]
__device__ u32 g_nw1t[256 * 128];  // node W1: [256 n][256 k]
__device__ u32 g_nw2t[128 * 128];  // node W2: [128 n][256 k]
__device__ u32 g_sw1t[256 * 64];   // sender W1: [256 n][128 k]
__device__ u32 g_sw2t[128 * 128];  // sender W2: [128 n][256 k]

// ------------------------- helpers -------------------------
__device__ __forceinline__ float silu_f(float x) {
    return x * (1.0f / (1.0f + __expf(-x)));
}
__device__ __forceinline__ float warp_reduce_add(float v) {
#pragma unroll
    for (int o = 16; o > 0; o >>= 1) v += __shfl_xor_sync(0xffffffffu, v, o);
    return v;
}
__device__ __forceinline__ int load_idx(const int* __restrict__ ei, int pos, int is64) {
    return is64 ? ei[2 * pos] : ei[pos];
}
// pack two fp32 -> fp16x2 word (v0 in low half)
__device__ __forceinline__ u32 pack_f16(float v0, float v1) {
    __half2 h = __floats2half2_rn(v0, v1);
    return *reinterpret_cast<u32*>(&h);
}
__device__ __forceinline__ u32 smem_u32(const void* p) {
    u32 a; asm("{ .reg .u64 t; cvta.to.shared.u64 t, %1; cvt.u32.u64 %0, t; }" : "=r"(a) : "l"(p));
    return a;
}
__device__ __forceinline__ void ldsm4(u32 a, u32& r0, u32& r1, u32& r2, u32& r3) {
    asm volatile("ldmatrix.sync.aligned.m8n8.x4.shared.b16 {%0,%1,%2,%3}, [%4];"
                 : "=r"(r0), "=r"(r1), "=r"(r2), "=r"(r3) : "r"(a));
}
__device__ __forceinline__ void mma_f16(float* c, const u32* a, u32 b0, u32 b1) {
    asm volatile(
        "mma.sync.aligned.m16n8k16.row.col.f32.f16.f16.f32 "
        "{%0,%1,%2,%3}, {%4,%5,%6,%7}, {%8,%9}, {%0,%1,%2,%3};"
        : "+f"(c[0]), "+f"(c[1]), "+f"(c[2]), "+f"(c[3])
        : "r"(a[0]), "r"(a[1]), "r"(a[2]), "r"(a[3]), "r"(b0), "r"(b1));
}
__device__ __forceinline__ void cpasync16(u32 dst, const void* src) {
    asm volatile("cp.async.cg.shared.global [%0], [%1], 16;" :: "r"(dst), "l"(src));
}
__device__ __forceinline__ void cp_wait_all() {
    asm volatile("cp.async.commit_group;");
    asm volatile("cp.async.wait_group 0;" ::: "memory");
}

// smem layout (identical for edge + generic MLP kernels)
#define SA1  0
#define SB1  17408
#define SA2  0
#define SB2  33792
#define ESMEM 87040
#define ST1  272    // byte stride, GEMM1 tiles (136 halves)
#define ST2  528    // byte stride, GEMM2 tiles (264 halves)
#define YSS  132    // Ys float stride (= ST2/4)

// LayerNorm on one row of Ys (stride YSS floats); lane holds cols lane*4..+3.
__device__ __forceinline__ float4 ln_row(const float* Ys, int rr, int lane,
                                         float4 gm, float4 bt)
{
    float4 v = ((const float4*)(Ys + rr * YSS))[lane];
    float s1 = v.x + v.y + v.z + v.w;
    float s2 = v.x * v.x + v.y * v.y + v.z * v.z + v.w * v.w;
    s1 = warp_reduce_add(s1);
    s2 = warp_reduce_add(s2);
    float mean = s1 * (1.0f / 128.0f);
    float var  = s2 * (1.0f / 128.0f) - mean * mean;
    float rstd = rsqrtf(var + 1e-5f);
    float4 p;
    p.x = (v.x - mean) * rstd * gm.x + bt.x;
    p.y = (v.y - mean) * rstd * gm.y + bt.y;
    p.z = (v.z - mean) * rstd * gm.z + bt.z;
    p.w = (v.w - mean) * rstd * gm.w + bt.w;
    return p;
}

// sweep of GEMM1: warp tile m32 x n64, K=128 (8 ksteps)
__device__ __forceinline__ void sweep1(u32 aBase, u32 bBase, float (&acc)[2][8][4])
{
#pragma unroll
    for (int ks = 0; ks < 8; ks++) {
        u32 A0[4], A1[4];
        ldsm4(aBase + ks * 32, A0[0], A0[1], A0[2], A0[3]);
        ldsm4(aBase + 16 * ST1 + ks * 32, A1[0], A1[1], A1[2], A1[3]);
#pragma unroll
        for (int p = 0; p < 4; p++) {
            u32 b0, b1, b2, b3;
            ldsm4(bBase + p * 16 * ST1 + ks * 32, b0, b1, b2, b3);
            mma_f16(acc[0][2 * p + 0], A0, b0, b1);
            mma_f16(acc[0][2 * p + 1], A0, b2, b3);
            mma_f16(acc[1][2 * p + 0], A1, b0, b1);
            mma_f16(acc[1][2 * p + 1], A1, b2, b3);
        }
    }
}

// sweep of GEMM2: warp tile m16 x n32, K=256 (16 ksteps)
__device__ __forceinline__ void sweep2(u32 aBase, u32 bBase, float (&acc)[4][4])
{
#pragma unroll
    for (int ks = 0; ks < 16; ks++) {
        u32 A0[4];
        ldsm4(aBase + ks * 32, A0[0], A0[1], A0[2], A0[3]);
#pragma unroll
        for (int p = 0; p < 2; p++) {
            u32 b0, b1, b2, b3;
            ldsm4(bBase + p * 16 * ST2 + ks * 32, b0, b1, b2, b3);
            mma_f16(acc[2 * p + 0], A0, b0, b1);
            mma_f16(acc[2 * p + 1], A0, b2, b3);
        }
    }
}

// ------------------------- utility kernels -------------------------
__global__ void detect_idx_kernel(const int* __restrict__ ei)
{
    __shared__ int any;
    if (threadIdx.x == 0) any = 0;
    __syncthreads();
    for (int i = threadIdx.x; i < 2048; i += blockDim.x)
        if (ei[2 * i + 1] != 0) any = 1;
    __syncthreads();
    if (threadIdx.x == 0) g_is64 = (any == 0) ? 1 : 0;
}

__global__ void zero_scratch_kernel()
{
    int i = blockIdx.x * blockDim.x + threadIdx.x;
    int stride = gridDim.x * blockDim.x;
    for (int j = i; j < NNODE * DN; j += stride) g_agg[j] = 0.0f;
    for (int j = i; j < NNODE; j += stride) g_cnt[j] = 0.0f;
}

// Transpose + fp16-convert ALL weights into k-major globals.
__global__ void prep_weights_kernel(const float* __restrict__ ew1, const float* __restrict__ ew2,
                                    const float* __restrict__ nw1, const float* __restrict__ nw2,
                                    const float* __restrict__ sw1, const float* __restrict__ sw2)
{
    int i = blockIdx.x * blockDim.x + threadIdx.x;
    // segment boundaries
    const int E1 = 256 * 192;            // g_w1t
    const int E2 = E1 + 128 * 128;       // g_w2t
    const int E3 = E2 + 256 * 128;       // g_nw1t
    const int E4 = E3 + 128 * 128;       // g_nw2t
    const int E5 = E4 + 256 * 64;        // g_sw1t
    const int E6 = E5 + 128 * 128;       // g_sw2t
    if (i < E1) {
        int n = i / 192, kp = i % 192;
        g_w1t[i] = pack_f16(ew1[(size_t)(2 * kp) * HN + n], ew1[(size_t)(2 * kp + 1) * HN + n]);
    } else if (i < E2) {
        int j = i - E1; int n = j / 128, kp = j % 128;
        g_w2t[j] = pack_f16(ew2[(size_t)(2 * kp) * DN + n], ew2[(size_t)(2 * kp + 1) * DN + n]);
    } else if (i < E3) {
        int j = i - E2; int n = j / 128, kp = j % 128;
        g_nw1t[j] = pack_f16(nw1[(size_t)(2 * kp) * HN + n], nw1[(size_t)(2 * kp + 1) * HN + n]);
    } else if (i < E4) {
        int j = i - E3; int n = j / 128, kp = j % 128;
        g_nw2t[j] = pack_f16(nw2[(size_t)(2 * kp) * DN + n], nw2[(size_t)(2 * kp + 1) * DN + n]);
    } else if (i < E5) {
        int j = i - E4; int n = j / 64, kp = j % 64;
        g_sw1t[j] = pack_f16(sw1[(size_t)(2 * kp) * HN + n], sw1[(size_t)(2 * kp + 1) * HN + n]);
    } else if (i < E6) {
        int j = i - E5; int n = j / 128, kp = j % 128;
        g_sw2t[j] = pack_f16(sw2[(size_t)(2 * kp) * DN + n], sw2[(size_t)(2 * kp + 1) * DN + n]);
    }
}

// ==================== mma.sync edge kernel (UNCHANGED from R15) ====================
__global__ void __launch_bounds__(256, 2)
edge_kernel_mma(const float* __restrict__ sx, const float* __restrict__ rx,
                const float* __restrict__ ea, const int* __restrict__ ei,
                const float* __restrict__ b1, const float* __restrict__ b2,
                const float* __restrict__ gam, const float* __restrict__ bet,
                float* __restrict__ edge_out)
{
    extern __shared__ char smc[];
    const u32 S = smem_u32(smc);

    const int tid = threadIdx.x, lane = tid & 31, warp = tid >> 5;
    const int base = blockIdx.x * EB;
    const int is64 = g_is64;

    const int r8 = lane & 7, q8 = lane >> 3;
    const int g = lane >> 2, tg = lane & 3;

    const int wm = (warp >> 2) * 32;
    const int wn = (warp & 3) * 64;

    const u32 a1A = S + SA1 + (u32)(wm + r8 + (q8 & 1) * 8) * ST1 + (u32)((q8 >> 1) * 8) * 2;
    const u32 b1A = S + SB1 + (u32)(wn + r8 + (q8 >> 1) * 8) * ST1 + (u32)((q8 & 1) * 8) * 2;

    float acc[2][8][4];
#pragma unroll
    for (int i = 0; i < 2; i++)
#pragma unroll
        for (int j = 0; j < 8; j++)
#pragma unroll
            for (int t = 0; t < 4; t++) acc[i][j][t] = 0.0f;

    const int grow = tid >> 2, gq = tid & 3;
    const int e0 = base + grow;
    const int si = load_idx(ei, e0, is64);
    const int di = load_idx(ei, NEDGE + e0, is64);

    for (int c = 0; c < 3; c++) {
        __syncthreads();
        {
            const uint4* gsrc = (const uint4*)g_w1t;
#pragma unroll
            for (int t = 0; t < 16; t++) {
                int idx = tid + t * 256;
                int n = idx >> 4, s = idx & 15;
                cpasync16(S + SB1 + (u32)n * ST1 + (u32)s * 16, gsrc + n * 48 + c * 16 + s);
            }
        }
        {
            const float* src = (c == 0) ? (sx + (size_t)si * DN)
                             : (c == 1) ? (rx + (size_t)di * DN)
                                        : (ea + (size_t)e0 * DN);
#pragma unroll
            for (int it = 0; it < 4; it++) {
                int k0 = gq * 32 + it * 8;
                float4 f0 = ((const float4*)(src + k0))[0];
                float4 f1 = ((const float4*)(src + k0))[1];
                u32 hw[4];
                hw[0] = pack_f16(f0.x, f0.y);
                hw[1] = pack_f16(f0.z, f0.w);
                hw[2] = pack_f16(f1.x, f1.y);
                hw[3] = pack_f16(f1.z, f1.w);
                u32 off = (u32)grow * ST1 + (u32)k0 * 2;
                *(uint4*)(smc + SA1 + off) = make_uint4(hw[0], hw[1], hw[2], hw[3]);
            }
        }
        cp_wait_all();
        __syncthreads();

        sweep1(a1A, b1A, acc);
    }
    __syncthreads();

    // epilogue1: bias + SiLU + fp16 -> A2
#pragma unroll
    for (int i = 0; i < 2; i++) {
        int row0 = wm + i * 16 + g;
#pragma unroll
        for (int j = 0; j < 8; j++) {
            int n0 = wn + j * 8 + tg * 2;
            float bv0 = b1[n0], bv1 = b1[n0 + 1];
            float h0 = silu_f(acc[i][j][0] + bv0);
            float h1 = silu_f(acc[i][j][1] + bv1);
            float h2 = silu_f(acc[i][j][2] + bv0);
            float h3 = silu_f(acc[i][j][3] + bv1);
            u32 off0 = (u32)row0 * ST2 + (u32)n0 * 2;
            u32 off1 = (u32)(row0 + 8) * ST2 + (u32)n0 * 2;
            *(u32*)(smc + SA2 + off0) = pack_f16(h0, h1);
            *(u32*)(smc + SA2 + off1) = pack_f16(h2, h3);
        }
    }

    // GEMM2: two 64-col n-halves
    const int wm2 = (warp >> 1) * 16;
    const int wn2 = (warp & 1) * 32;
    const u32 a2A = S + SA2 + (u32)(wm2 + r8 + (q8 & 1) * 8) * ST2 + (u32)((q8 >> 1) * 8) * 2;
    const u32 b2A = S + SB2 + (u32)(wn2 + r8 + (q8 >> 1) * 8) * ST2 + (u32)((q8 & 1) * 8) * 2;

    float acc2[2][4][4];
#pragma unroll
    for (int h = 0; h < 2; h++)
#pragma unroll
        for (int j = 0; j < 4; j++)
#pragma unroll
            for (int t = 0; t < 4; t++) acc2[h][j][t] = 0.0f;

    for (int h = 0; h < 2; h++) {
        {
            const uint4* gsrc = (const uint4*)g_w2t;
#pragma unroll
            for (int t = 0; t < 8; t++) {
                int idx = tid + t * 256;
                int n = idx >> 5, s = idx & 31;
                cpasync16(S + SB2 + (u32)n * ST2 + (u32)s * 16, gsrc + (h * 64 + n) * 32 + s);
            }
        }
        cp_wait_all();
        __syncthreads();

        sweep2(a2A, b2A, acc2[h]);
        __syncthreads();
    }

    // epilogue2a: bias -> Ys fp32
#pragma unroll
    for (int h = 0; h < 2; h++) {
        int row0 = wm2 + g;
#pragma unroll
        for (int j = 0; j < 4; j++) {
            int n0 = h * 64 + wn2 + j * 8 + tg * 2;
            float bv0 = b2[n0], bv1 = b2[n0 + 1];
            float2 y0 = make_float2(acc2[h][j][0] + bv0, acc2[h][j][1] + bv1);
            float2 y1 = make_float2(acc2[h][j][2] + bv0, acc2[h][j][3] + bv1);
            *(float2*)(smc + (u32)row0 * ST2 + (u32)n0 * 4)       = y0;
            *(float2*)(smc + (u32)(row0 + 8) * ST2 + (u32)n0 * 4) = y1;
        }
    }
    __syncthreads();

    // epilogue2b: LN + residual + atomic scatter
    {
        const float* Ys = (const float*)smc;
        float4 gm = ((const float4*)gam)[lane];
        float4 bt = ((const float4*)bet)[lane];
#pragma unroll 1
        for (int it = 0; it < 8; it++) {
            int rr = warp * 8 + it;
            int e = base + rr;
            float4 p = ln_row(Ys, rr, lane, gm, bt);
            int d = load_idx(ei, NEDGE + e, is64);
            float4 ev = ((const float4*)(ea + (size_t)e * DN))[lane];
            float4 o;
            o.x = ev.x + p.x; o.y = ev.y + p.y; o.z = ev.z + p.z; o.w = ev.w + p.w;
            ((float4*)(edge_out + (size_t)e * DN))[lane] = o;
            float* ag = g_agg + (size_t)d * DN + lane * 4;
            atomicAdd(ag + 0, p.x);
            atomicAdd(ag + 1, p.y);
            atomicAdd(ag + 2, p.z);
            atomicAdd(ag + 3, p.w);
            if (lane == 0) atomicAdd(&g_cnt[d], 1.0f);
        }
    }
}

// ==================== generic node/sender MLP kernel (fp16 mma) ====================
// NCHUNK=1: sender (input = xin only). NCHUNK=2: node (chunk0 = xin, chunk1 = mean-agg).
template <int NCHUNK>
__global__ void __launch_bounds__(256, 2)
mlp_kernel_mma(const float* __restrict__ xin,
               const uint4* __restrict__ w1t, int w1s,   // row stride in uint4
               const uint4* __restrict__ w2t,
               const float* __restrict__ b1, const float* __restrict__ b2,
               const float* __restrict__ gam, const float* __restrict__ bet,
               float* __restrict__ outp)
{
    extern __shared__ char smc[];
    const u32 S = smem_u32(smc);

    const int tid = threadIdx.x, lane = tid & 31, warp = tid >> 5;
    const int base = blockIdx.x * EB;

    const int r8 = lane & 7, q8 = lane >> 3;
    const int g = lane >> 2, tg = lane & 3;

    const int wm = (warp >> 2) * 32;
    const int wn = (warp & 3) * 64;

    const u32 a1A = S + SA1 + (u32)(wm + r8 + (q8 & 1) * 8) * ST1 + (u32)((q8 >> 1) * 8) * 2;
    const u32 b1A = S + SB1 + (u32)(wn + r8 + (q8 >> 1) * 8) * ST1 + (u32)((q8 & 1) * 8) * 2;

    float acc[2][8][4];
#pragma unroll
    for (int i = 0; i < 2; i++)
#pragma unroll
        for (int j = 0; j < 8; j++)
#pragma unroll
            for (int t = 0; t < 4; t++) acc[i][j][t] = 0.0f;

    const int grow = tid >> 2, gq = tid & 3;
    const int n0r = base + grow;

    for (int c = 0; c < NCHUNK; c++) {
        __syncthreads();
        // stage B1 chunk
#pragma unroll
        for (int t = 0; t < 16; t++) {
            int idx = tid + t * 256;
            int n = idx >> 4, s = idx & 15;
            cpasync16(S + SB1 + (u32)n * ST1 + (u32)s * 16, w1t + n * w1s + c * 16 + s);
        }
        // gather + fp16-convert A chunk
        if (c == 0) {
            const float* src = xin + (size_t)n0r * DN;
#pragma unroll
            for (int it = 0; it < 4; it++) {
                int k0 = gq * 32 + it * 8;
                float4 f0 = ((const float4*)(src + k0))[0];
                float4 f1 = ((const float4*)(src + k0))[1];
                u32 hw[4];
                hw[0] = pack_f16(f0.x, f0.y);
                hw[1] = pack_f16(f0.z, f0.w);
                hw[2] = pack_f16(f1.x, f1.y);
                hw[3] = pack_f16(f1.z, f1.w);
                u32 off = (u32)grow * ST1 + (u32)k0 * 2;
                *(uint4*)(smc + SA1 + off) = make_uint4(hw[0], hw[1], hw[2], hw[3]);
            }
        } else {
            float inv = 1.0f / fmaxf(g_cnt[n0r], 1.0f);
            const float* src = g_agg + (size_t)n0r * DN;
#pragma unroll
            for (int it = 0; it < 4; it++) {
                int k0 = gq * 32 + it * 8;
                float4 f0 = ((const float4*)(src + k0))[0];
                float4 f1 = ((const float4*)(src + k0))[1];
                u32 hw[4];
                hw[0] = pack_f16(f0.x * inv, f0.y * inv);
                hw[1] = pack_f16(f0.z * inv, f0.w * inv);
                hw[2] = pack_f16(f1.x * inv, f1.y * inv);
                hw[3] = pack_f16(f1.z * inv, f1.w * inv);
                u32 off = (u32)grow * ST1 + (u32)k0 * 2;
                *(uint4*)(smc + SA1 + off) = make_uint4(hw[0], hw[1], hw[2], hw[3]);
            }
        }
        cp_wait_all();
        __syncthreads();

        sweep1(a1A, b1A, acc);
    }
    __syncthreads();

    // epilogue1: bias + SiLU + fp16 -> A2
#pragma unroll
    for (int i = 0; i < 2; i++) {
        int row0 = wm + i * 16 + g;
#pragma unroll
        for (int j = 0; j < 8; j++) {
            int n0 = wn + j * 8 + tg * 2;
            float bv0 = b1[n0], bv1 = b1[n0 + 1];
            float h0 = silu_f(acc[i][j][0] + bv0);
            float h1 = silu_f(acc[i][j][1] + bv1);
            float h2 = silu_f(acc[i][j][2] + bv0);
            float h3 = silu_f(acc[i][j][3] + bv1);
            u32 off0 = (u32)row0 * ST2 + (u32)n0 * 2;
            u32 off1 = (u32)(row0 + 8) * ST2 + (u32)n0 * 2;
            *(u32*)(smc + SA2 + off0) = pack_f16(h0, h1);
            *(u32*)(smc + SA2 + off1) = pack_f16(h2, h3);
        }
    }

    // GEMM2: two 64-col n-halves
    const int wm2 = (warp >> 1) * 16;
    const int wn2 = (warp & 1) * 32;
    const u32 a2A = S + SA2 + (u32)(wm2 + r8 + (q8 & 1) * 8) * ST2 + (u32)((q8 >> 1) * 8) * 2;
    const u32 b2A = S + SB2 + (u32)(wn2 + r8 + (q8 >> 1) * 8) * ST2 + (u32)((q8 & 1) * 8) * 2;

    float acc2[2][4][4];
#pragma unroll
    for (int h = 0; h < 2; h++)
#pragma unroll
        for (int j = 0; j < 4; j++)
#pragma unroll
            for (int t = 0; t < 4; t++) acc2[h][j][t] = 0.0f;

    for (int h = 0; h < 2; h++) {
#pragma unroll
        for (int t = 0; t < 8; t++) {
            int idx = tid + t * 256;
            int n = idx >> 5, s = idx & 31;
            cpasync16(S + SB2 + (u32)n * ST2 + (u32)s * 16, w2t + (h * 64 + n) * 32 + s);
        }
        cp_wait_all();
        __syncthreads();

        sweep2(a2A, b2A, acc2[h]);
        __syncthreads();
    }

    // epilogue2a: bias -> Ys fp32
#pragma unroll
    for (int h = 0; h < 2; h++) {
        int row0 = wm2 + g;
#pragma unroll
        for (int j = 0; j < 4; j++) {
            int n0 = h * 64 + wn2 + j * 8 + tg * 2;
            float bv0 = b2[n0], bv1 = b2[n0 + 1];
            float2 y0 = make_float2(acc2[h][j][0] + bv0, acc2[h][j][1] + bv1);
            float2 y1 = make_float2(acc2[h][j][2] + bv0, acc2[h][j][3] + bv1);
            *(float2*)(smc + (u32)row0 * ST2 + (u32)n0 * 4)       = y0;
            *(float2*)(smc + (u32)(row0 + 8) * ST2 + (u32)n0 * 4) = y1;
        }
    }
    __syncthreads();

    // epilogue2b: LN + residual -> out
    {
        const float* Ys = (const float*)smc;
        float4 gm = ((const float4*)gam)[lane];
        float4 bt = ((const float4*)bet)[lane];
#pragma unroll 1
        for (int it = 0; it < 8; it++) {
            int rr = warp * 8 + it;
            int n = base + rr;
            float4 p = ln_row(Ys, rr, lane, gm, bt);
            float4 xv = ((const float4*)(xin + (size_t)n * DN))[lane];
            float4 o;
            o.x = xv.x + p.x; o.y = xv.y + p.y; o.z = xv.z + p.z; o.w = xv.w + p.w;
            ((float4*)(outp + (size_t)n * DN))[lane] = o;
        }
    }
}

// ------------------------- launch -------------------------
extern "C" void kernel_launch(void* const* d_in, const int* in_sizes, int n_in,
                              void* d_out, int out_size)
{
    const float* sx    = (const float*)d_in[0];
    const float* rx    = (const float*)d_in[1];
    const float* ea    = (const float*)d_in[2];
    const int*   ei    = (const int*)d_in[3];
    const float* ew1   = (const float*)d_in[4];
    const float* eb1   = (const float*)d_in[5];
    const float* ew2   = (const float*)d_in[6];
    const float* eb2   = (const float*)d_in[7];
    const float* eg    = (const float*)d_in[8];
    const float* ebeta = (const float*)d_in[9];
    const float* nw1   = (const float*)d_in[10];
    const float* nb1   = (const float*)d_in[11];
    const float* nw2   = (const float*)d_in[12];
    const float* nb2   = (const float*)d_in[13];
    const float* ng    = (const float*)d_in[14];
    const float* nbeta = (const float*)d_in[15];
    const float* sw1   = (const float*)d_in[16];
    const float* sb1   = (const float*)d_in[17];
    const float* sw2   = (const float*)d_in[18];
    const float* sb2   = (const float*)d_in[19];
    const float* sg    = (const float*)d_in[20];
    const float* sbeta = (const float*)d_in[21];

    float* out = (float*)d_out;
    float* send_out = out;
    float* recv_out = out + (size_t)NNODE * DN;
    float* edge_out = out + (size_t)2 * NNODE * DN;

    cudaFuncSetAttribute(edge_kernel_mma,  cudaFuncAttributeMaxDynamicSharedMemorySize, ESMEM);
    cudaFuncSetAttribute(mlp_kernel_mma<1>, cudaFuncAttributeMaxDynamicSharedMemorySize, ESMEM);
    cudaFuncSetAttribute(mlp_kernel_mma<2>, cudaFuncAttributeMaxDynamicSharedMemorySize, ESMEM);

    detect_idx_kernel<<<1, 256>>>(ei);
    prep_weights_kernel<<<600, 256>>>(ew1, ew2, nw1, nw2, sw1, sw2);
    zero_scratch_kernel<<<296, 256>>>();

    // device-global weight addresses (host-side symbol resolution not needed:
    // pass via cudaGetSymbolAddress-free trick — use device pointers obtained
    // from the globals directly in device code is not possible from host, so
    // fetch symbol addresses once per launch; cudaGetSymbolAddress is not an
    // allocation and is graph-capture-safe (host-side query).
    static uint4 *p_nw1t = nullptr, *p_nw2t = nullptr, *p_sw1t = nullptr, *p_sw2t = nullptr;
    if (!p_nw1t) {
        void* tmp;
        cudaGetSymbolAddress(&tmp, g_nw1t); p_nw1t = (uint4*)tmp;
        cudaGetSymbolAddress(&tmp, g_nw2t); p_nw2t = (uint4*)tmp;
        cudaGetSymbolAddress(&tmp, g_sw1t); p_sw1t = (uint4*)tmp;
        cudaGetSymbolAddress(&tmp, g_sw2t); p_sw2t = (uint4*)tmp;
    }

    edge_kernel_mma<<<NEDGE / EB, 256, ESMEM>>>(
        sx, rx, ea, ei, eb1, eb2, eg, ebeta, edge_out);

    mlp_kernel_mma<1><<<NNODE / EB, 256, ESMEM>>>(
        sx, p_sw1t, 16, p_sw2t, sb1, sb2, sg, sbeta, send_out);

    mlp_kernel_mma<2><<<NNODE / EB, 256, ESMEM>>>(
        rx, p_nw1t, 32, p_nw2t, nb1, nb2, ng, nbeta, recv_out);
}